// round 9
// baseline (speedup 1.0000x reference)
#include <cuda_runtime.h>
#include <cuda_bf16.h>
#include <math.h>
#include <stdint.h>

typedef __nv_bfloat16 bf16;

#define S_LEN 4096
#define D_DIM 512
#define FF_DIM 1024
#define EPS_LN 1e-5f

// ---------------- persistent scratch (no allocations) ----------------
__device__ bf16 g_h_hi [S_LEN * D_DIM],  g_h_lo [S_LEN * D_DIM];
__device__ bf16 g_wqkvT_hi[1536 * 512],  g_wqkvT_lo[1536 * 512];
__device__ bf16 g_woutT_hi[512 * 512],   g_woutT_lo[512 * 512];
__device__ bf16 g_wff1T_hi[1024 * 512],  g_wff1T_lo[1024 * 512];
__device__ bf16 g_wff2T_hi[512 * 1024],  g_wff2T_lo[512 * 1024];
__device__ bf16 g_qk_hi[S_LEN * 1024],   g_qk_lo[S_LEN * 1024];
__device__ bf16 g_vt_hi[512 * S_LEN],    g_vt_lo[512 * S_LEN];   // [h*64+dh][seq]
__device__ bf16 g_ao_hi[S_LEN * D_DIM],  g_ao_lo[S_LEN * D_DIM];
__device__ bf16 g_h2_hi[S_LEN * D_DIM],  g_h2_lo[S_LEN * D_DIM];
__device__ bf16 g_ff_hi[S_LEN * FF_DIM], g_ff_lo[S_LEN * FF_DIM];
__device__ float g_x1[S_LEN * D_DIM];
__device__ float g_po[1152 * 128 * 64];   // split-K partial O (unnormalized)
__device__ float g_pml[1152 * 256];       // per-row (m, l) per split

__device__ __forceinline__ uint32_t smem_u32(const void* p) {
    uint32_t a;
    asm("{ .reg .u64 t; cvta.to.shared.u64 t, %1; cvt.u32.u64 %0, t; }" : "=r"(a) : "l"(p));
    return a;
}

#define LDMATRIX_X4(r0, r1, r2, r3, a) \
    asm volatile("ldmatrix.sync.aligned.m8n8.x4.shared.b16 {%0,%1,%2,%3}, [%4];" \
        : "=r"(r0), "=r"(r1), "=r"(r2), "=r"(r3) : "r"(a))
#define MMA_BF16(d, a, b) \
    asm volatile("mma.sync.aligned.m16n8k16.row.col.f32.bf16.bf16.f32 " \
        "{%0,%1,%2,%3}, {%4,%5,%6,%7}, {%8,%9}, {%0,%1,%2,%3};" \
        : "+f"((d)[0]), "+f"((d)[1]), "+f"((d)[2]), "+f"((d)[3]) \
        : "r"((a)[0]), "r"((a)[1]), "r"((a)[2]), "r"((a)[3]), "r"((b)[0]), "r"((b)[1]))

#define CP16(dst, src) asm volatile("cp.async.cg.shared.global [%0], [%1], 16;" :: "r"(dst), "l"(src))
#define CP_COMMIT()    asm volatile("cp.async.commit_group;")
#define CP_WAIT1()     asm volatile("cp.async.wait_group 1;" ::: "memory")
#define CP_WAIT0()     asm volatile("cp.async.wait_group 0;" ::: "memory")

__device__ __forceinline__ void split2(float x, float y, uint32_t& hp, uint32_t& lp) {
    __nv_bfloat162 h = __floats2bfloat162_rn(x, y);
    float lx = x - __bfloat162float(__low2bfloat16(h));
    float ly = y - __bfloat162float(__high2bfloat16(h));
    __nv_bfloat162 l = __floats2bfloat162_rn(lx, ly);
    hp = *(uint32_t*)&h; lp = *(uint32_t*)&l;
}
__device__ __forceinline__ uint32_t pack_bf16(float x, float y) {
    __nv_bfloat162 h = __floats2bfloat162_rn(x, y);
    return *(uint32_t*)&h;
}
__device__ __forceinline__ uint32_t pack_bf16_lo(float x, float y, uint32_t hp) {
    __nv_bfloat162 h = *(__nv_bfloat162*)&hp;
    float lx = x - __bfloat162float(__low2bfloat16(h));
    float ly = y - __bfloat162float(__high2bfloat16(h));
    __nv_bfloat162 lo = __floats2bfloat162_rn(lx, ly);
    return *(uint32_t*)&lo;
}

__device__ __forceinline__ int nsp_of(int qb) { return (2 * qb + 9) >> 3; }  // ceil((2qb+2)/8)

// ---------------- merged weight prep: 4 weights in one launch ----------------
__global__ void wprep4(const float* __restrict__ s0, bf16* __restrict__ h0, bf16* __restrict__ l0,
                       const float* __restrict__ s1, bf16* __restrict__ h1, bf16* __restrict__ l1,
                       const float* __restrict__ s2, bf16* __restrict__ h2, bf16* __restrict__ l2,
                       const float* __restrict__ s3, bf16* __restrict__ h3, bf16* __restrict__ l3) {
    __shared__ float t[32][33];
    int b = blockIdx.x;
    const float* src; bf16 *dh, *dl; int K, N, nx, rb;
    if (b < 768)       { src = s0; dh = h0; dl = l0; K = 512;  N = 1536; nx = 48; rb = b; }
    else if (b < 1024) { src = s1; dh = h1; dl = l1; K = 512;  N = 512;  nx = 16; rb = b - 768; }
    else if (b < 1536) { src = s2; dh = h2; dl = l2; K = 512;  N = 1024; nx = 32; rb = b - 1024; }
    else               { src = s3; dh = h3; dl = l3; K = 1024; N = 512;  nx = 16; rb = b - 1536; }
    int n0 = (rb % nx) * 32, k0 = (rb / nx) * 32;
    int tx = threadIdx.x & 31, ty = threadIdx.x >> 5;
    #pragma unroll
    for (int i = 0; i < 32; i += 8)
        t[ty + i][tx] = src[(size_t)(k0 + ty + i) * N + n0 + tx];
    __syncthreads();
    #pragma unroll
    for (int i = 0; i < 32; i += 8) {
        float v = t[tx][ty + i];
        bf16 h = __float2bfloat16(v);
        bf16 l = __float2bfloat16(v - __bfloat162float(h));
        size_t idx = (size_t)(n0 + ty + i) * K + k0 + tx;
        dh[idx] = h; dl[idx] = l;
    }
}

// ---------------- LayerNorm -> split bf16 ----------------
__global__ void ln_split(const float* __restrict__ x, const float* __restrict__ g,
                         const float* __restrict__ b, bf16* __restrict__ oh,
                         bf16* __restrict__ ol) {
    __shared__ float red[32];
    __shared__ float s_mean, s_rstd;
    int row = blockIdx.x;
    int tid = threadIdx.x;
    float2 v = *(const float2*)(x + (size_t)row * D_DIM + tid * 2);

    float sum = v.x + v.y;
    #pragma unroll
    for (int o = 16; o > 0; o >>= 1) sum += __shfl_down_sync(0xffffffffu, sum, o);
    if ((tid & 31) == 0) red[tid >> 5] = sum;
    __syncthreads();
    if (tid < 32) {
        float t = (tid < 8) ? red[tid] : 0.f;
        #pragma unroll
        for (int o = 4; o > 0; o >>= 1) t += __shfl_down_sync(0xffffffffu, t, o);
        if (tid == 0) s_mean = t * (1.f / D_DIM);
    }
    __syncthreads();
    float mean = s_mean;
    float d0 = v.x - mean, d1 = v.y - mean;

    float vs = d0 * d0 + d1 * d1;
    #pragma unroll
    for (int o = 16; o > 0; o >>= 1) vs += __shfl_down_sync(0xffffffffu, vs, o);
    if ((tid & 31) == 0) red[tid >> 5] = vs;
    __syncthreads();
    if (tid < 32) {
        float t = (tid < 8) ? red[tid] : 0.f;
        #pragma unroll
        for (int o = 4; o > 0; o >>= 1) t += __shfl_down_sync(0xffffffffu, t, o);
        if (tid == 0) s_rstd = rsqrtf(t * (1.f / D_DIM) + EPS_LN);
    }
    __syncthreads();
    float rstd = s_rstd;

    int c = tid * 2;
    float2 gg = *(const float2*)(g + c);
    float2 bb = *(const float2*)(b + c);
    float ox = d0 * rstd * gg.x + bb.x;
    float oy = d1 * rstd * gg.y + bb.y;
    uint32_t hp, lp;
    split2(ox, oy, hp, lp);
    *(uint32_t*)(oh + (size_t)row * D_DIM + c) = hp;
    *(uint32_t*)(ol + (size_t)row * D_DIM + c) = lp;
}

// ---------------- cp.async split-bf16 GEMM (2- or 3-stage) ----------------
template <int BN, int K_TOT, int EPI, int STAGES>
__global__ void __launch_bounds__(256, 2)
gemm_cp(const bf16* __restrict__ Ah, const bf16* __restrict__ Al,
        const bf16* __restrict__ Bh, const bf16* __restrict__ Bl,
        const float* __restrict__ bias, const float* __restrict__ res,
        float* __restrict__ Cf, bf16* __restrict__ Ch, bf16* __restrict__ Cl,
        bf16* __restrict__ Vh, bf16* __restrict__ Vl, int N) {
    constexpr int WARPS_N = BN / 32;
    constexpr int WARPS_M = 8 / WARPS_N;
    constexpr int WM = 128 / WARPS_M;
    constexpr int MI = WM / 16;
    constexpr int A_SZ = 128 * 80;
    constexpr int B_SZ = BN * 80;
    constexpr int B_OFF = 2 * A_SZ;
    constexpr int BUF = 2 * A_SZ + 2 * B_SZ;
    constexpr int NS = K_TOT / 32;

    extern __shared__ __align__(16) char smx[];
    const uint32_t sbase = smem_u32(smx);

    int tid = threadIdx.x;
    int wid = tid >> 5;
    int l = tid & 31;
    int bm = blockIdx.y * 128, bn = blockIdx.x * BN;
    int warp_m = wid / WARPS_N, warp_n = wid % WARPS_N;

    float d[MI][4][4];
    #pragma unroll
    for (int i = 0; i < MI; i++)
        #pragma unroll
        for (int j = 0; j < 4; j++)
            #pragma unroll
            for (int k = 0; k < 4; k++) d[i][j][k] = 0.f;

    int lb = l & 15;
    uint32_t a_rel = (uint32_t)(warp_m * WM + lb) * 80 + (uint32_t)(l >> 4) * 16;
    uint32_t b_rel = B_OFF + (uint32_t)(warp_n * 32 + (l >> 4) * 8 + (l & 7)) * 80 +
                     (uint32_t)((l >> 3) & 1) * 16;

    int a_cc = tid & 3, a_row = tid >> 2;
    constexpr int BCH = BN * 4;

    auto issue = [&](int s) {
        int k0 = s * 32;
        uint32_t bufb = sbase + (uint32_t)((s % STAGES) * BUF);
        #pragma unroll
        for (int t = 0; t < 2; t++) {
            int row = a_row + t * 64;
            size_t so = (size_t)(bm + row) * K_TOT + k0 + a_cc * 8;
            uint32_t dst = bufb + (uint32_t)(row * 80 + a_cc * 16);
            CP16(dst, Ah + so);
            CP16(dst + A_SZ, Al + so);
        }
        #pragma unroll
        for (int t = 0; t < BCH / 256; t++) {
            int c = tid + t * 256;
            int cc = c & 3, row = c >> 2;
            size_t so = (size_t)(bn + row) * K_TOT + k0 + cc * 8;
            uint32_t dst = bufb + B_OFF + (uint32_t)(row * 80 + cc * 16);
            CP16(dst, Bh + so);
            CP16(dst + B_SZ, Bl + so);
        }
    };

    auto compute = [&](int s) {
        uint32_t cb = sbase + (uint32_t)((s % STAGES) * BUF);
        #pragma unroll
        for (int ks = 0; ks < 2; ks++) {
            uint32_t bh[4][2], blo[4][2];
            #pragma unroll
            for (int pj = 0; pj < 2; pj++) {
                uint32_t ba = cb + b_rel + pj * 16 * 80 + ks * 32;
                LDMATRIX_X4(bh[2 * pj][0], bh[2 * pj][1], bh[2 * pj + 1][0], bh[2 * pj + 1][1], ba);
                LDMATRIX_X4(blo[2 * pj][0], blo[2 * pj][1], blo[2 * pj + 1][0], blo[2 * pj + 1][1], ba + B_SZ);
            }
            #pragma unroll
            for (int mi = 0; mi < MI; mi++) {
                uint32_t ah[4], al[4];
                uint32_t aa = cb + a_rel + mi * 16 * 80 + ks * 32;
                LDMATRIX_X4(ah[0], ah[1], ah[2], ah[3], aa);
                LDMATRIX_X4(al[0], al[1], al[2], al[3], aa + A_SZ);
                #pragma unroll
                for (int nj = 0; nj < 4; nj++) {
                    MMA_BF16(d[mi][nj], ah, bh[nj]);
                    MMA_BF16(d[mi][nj], ah, blo[nj]);
                    MMA_BF16(d[mi][nj], al, bh[nj]);
                }
            }
        }
    };

    if (STAGES == 3) {
        issue(0); CP_COMMIT();
        issue(1); CP_COMMIT();
        for (int s = 0; s < NS; s++) {
            if (s == NS - 1) CP_WAIT0(); else CP_WAIT1();
            __syncthreads();
            compute(s);
            if (s + 2 < NS) { issue(s + 2); CP_COMMIT(); }
        }
    } else {
        issue(0); CP_COMMIT();
        for (int s = 0; s < NS; s++) {
            if (s + 1 < NS) { issue(s + 1); CP_COMMIT(); CP_WAIT1(); }
            else CP_WAIT0();
            __syncthreads();
            compute(s);
            __syncthreads();
        }
    }

    // ---- epilogue ----
    #pragma unroll
    for (int mi = 0; mi < MI; mi++) {
        int row0 = bm + warp_m * WM + mi * 16 + (l >> 2);
        #pragma unroll
        for (int nj = 0; nj < 4; nj++) {
            int col = bn + warp_n * 32 + nj * 8 + (l & 3) * 2;
            float2 bb = *(const float2*)(bias + col);
            #pragma unroll
            for (int half = 0; half < 2; half++) {
                int row = row0 + half * 8;
                float vx = d[mi][nj][half * 2 + 0] + bb.x;
                float vy = d[mi][nj][half * 2 + 1] + bb.y;
                if (EPI == 0) {
                    if (col < 1024) {
                        uint32_t hp, lp;
                        split2(vx, vy, hp, lp);
                        *(uint32_t*)(Ch + (size_t)row * 1024 + col) = hp;
                        *(uint32_t*)(Cl + (size_t)row * 1024 + col) = lp;
                    } else {
                        int hc = col - 1024;
                        bf16 hx = __float2bfloat16(vx);
                        bf16 lx = __float2bfloat16(vx - __bfloat162float(hx));
                        bf16 hy = __float2bfloat16(vy);
                        bf16 ly = __float2bfloat16(vy - __bfloat162float(hy));
                        size_t i0 = (size_t)hc * S_LEN + row;
                        Vh[i0] = hx; Vl[i0] = lx;
                        Vh[i0 + S_LEN] = hy; Vl[i0 + S_LEN] = ly;
                    }
                } else if (EPI == 1) {
                    vx = 0.5f * vx * (1.f + erff(vx * 0.70710678118654752f));
                    vy = 0.5f * vy * (1.f + erff(vy * 0.70710678118654752f));
                    uint32_t hp, lp;
                    split2(vx, vy, hp, lp);
                    *(uint32_t*)(Ch + (size_t)row * N + col) = hp;
                    *(uint32_t*)(Cl + (size_t)row * N + col) = lp;
                } else {
                    float2 rr = *(const float2*)(res + (size_t)row * N + col);
                    float2 o2; o2.x = vx + rr.x; o2.y = vy + rr.y;
                    *(float2*)(Cf + (size_t)row * N + col) = o2;
                }
            }
        }
    }
}

// ---------------- cp.async flash attention, split-K (max 8 K-tiles/split) ----------------
#define AST 144
#define QSZ (128 * AST)
#define KSZ (64 * AST)
#define KVBUF (4 * KSZ)
#define KV0 (2 * QSZ)
#define ATT_SMEM (KV0 + 2 * KVBUF)

__global__ void __launch_bounds__(256, 2)
attn_cp(const bf16* __restrict__ QKh, const bf16* __restrict__ QKl,
        const bf16* __restrict__ Vth, const bf16* __restrict__ Vtl,
        bf16* __restrict__ AOh, bf16* __restrict__ AOl,
        float* __restrict__ Po, float* __restrict__ Pml) {
    extern __shared__ char sm[];
    const uint32_t sbase = smem_u32(sm);

    int gx = (int)gridDim.x - 1 - (int)blockIdx.x;   // high-qb splits first
    int qb = 0, acc = 0;
    while (acc + nsp_of(qb) <= gx) { acc += nsp_of(qb); qb++; }
    int sp = gx - acc;
    int nsp = nsp_of(qb);
    int total = 2 * qb + 2;
    int chunk = (total + nsp - 1) / nsp;
    int kb_begin = sp * chunk;
    int kb_end = min(total, kb_begin + chunk);
    int pidx = gx * 8 + (int)blockIdx.y;

    int h = blockIdx.y;
    int tid = threadIdx.x;
    int w = tid >> 5;
    int l = tid & 31;
    int lb = l & 15;

    int q_cc = tid & 7, q_row = tid >> 3;
    auto issueQ = [&]() {
        #pragma unroll
        for (int t = 0; t < 4; t++) {
            int row = q_row + t * 32;
            size_t so = (size_t)(qb * 128 + row) * 1024 + h * 64 + q_cc * 8;
            uint32_t dst = sbase + (uint32_t)(row * AST + q_cc * 16);
            CP16(dst, QKh + so);
            CP16(dst + QSZ, QKl + so);
        }
    };
    auto issueKV = [&](int kb) {
        uint32_t base = sbase + KV0 + (uint32_t)((kb & 1) * KVBUF);
        #pragma unroll
        for (int t = 0; t < 2; t++) {
            int row = q_row + t * 32;
            uint32_t doff = (uint32_t)(row * AST + q_cc * 16);
            size_t sk = (size_t)(kb * 64 + row) * 1024 + 512 + h * 64 + q_cc * 8;
            CP16(base + doff, QKh + sk);
            CP16(base + KSZ + doff, QKl + sk);
            size_t sv = (size_t)(h * 64 + row) * S_LEN + kb * 64 + q_cc * 8;
            CP16(base + 2 * KSZ + doff, Vth + sv);
            CP16(base + 3 * KSZ + doff, Vtl + sv);
        }
    };

    issueQ();
    issueKV(kb_begin); CP_COMMIT();

    float o[8][4];
    #pragma unroll
    for (int j = 0; j < 8; j++)
        #pragma unroll
        for (int k = 0; k < 4; k++) o[j][k] = 0.f;
    float m0 = -1e30f, m1 = -1e30f, l0 = 0.f, l1 = 0.f;

    uint32_t aq = sbase + (uint32_t)((16 * w + lb) * AST) + (uint32_t)(l >> 4) * 16;
    uint32_t kv_rel = (uint32_t)(((l >> 4) * 8 + (l & 7)) * AST) + (uint32_t)((l >> 3) & 1) * 16;

    int row0g = qb * 128 + 16 * w + (l >> 2);

    for (int kb = kb_begin; kb < kb_end; kb++) {
        if (kb + 1 < kb_end) { issueKV(kb + 1); CP_COMMIT(); CP_WAIT1(); }
        else CP_WAIT0();
        __syncthreads();

        uint32_t kvb = sbase + KV0 + (uint32_t)((kb & 1) * KVBUF);
        uint32_t bk = kvb + kv_rel;
        uint32_t bv = kvb + 2 * KSZ + kv_rel;

        // ---- S = Q K^T (3-pass split) ----
        float s[8][4];
        #pragma unroll
        for (int j = 0; j < 8; j++)
            #pragma unroll
            for (int k = 0; k < 4; k++) s[j][k] = 0.f;
        #pragma unroll
        for (int ks = 0; ks < 4; ks++) {
            uint32_t ah[4], al[4];
            LDMATRIX_X4(ah[0], ah[1], ah[2], ah[3], aq + ks * 32);
            LDMATRIX_X4(al[0], al[1], al[2], al[3], aq + ks * 32 + QSZ);
            #pragma unroll
            for (int jp = 0; jp < 4; jp++) {
                uint32_t bh[2][2], blo[2][2];
                uint32_t ba = bk + jp * 16 * AST + ks * 32;
                LDMATRIX_X4(bh[0][0], bh[0][1], bh[1][0], bh[1][1], ba);
                LDMATRIX_X4(blo[0][0], blo[0][1], blo[1][0], blo[1][1], ba + KSZ);
                #pragma unroll
                for (int q = 0; q < 2; q++) {
                    int j = 2 * jp + q;
                    MMA_BF16(s[j], ah, bh[q]);
                    MMA_BF16(s[j], ah, blo[q]);
                    MMA_BF16(s[j], al, bh[q]);
                }
            }
        }

        // ---- scale + causal mask ----
        int cbase = kb * 64 + 2 * (l & 3);
        bool need_mask = (kb >= 2 * qb);
        #pragma unroll
        for (int j = 0; j < 8; j++) {
            #pragma unroll
            for (int k = 0; k < 4; k++) s[j][k] *= 0.125f;
            if (need_mask) {
                int c0 = cbase + 8 * j;
                if (c0 > row0g)     s[j][0] = -1e30f;
                if (c0 + 1 > row0g) s[j][1] = -1e30f;
                if (c0 > row0g + 8)     s[j][2] = -1e30f;
                if (c0 + 1 > row0g + 8) s[j][3] = -1e30f;
            }
        }

        // ---- online softmax ----
        float mn0 = m0, mn1 = m1;
        #pragma unroll
        for (int j = 0; j < 8; j++) {
            mn0 = fmaxf(mn0, fmaxf(s[j][0], s[j][1]));
            mn1 = fmaxf(mn1, fmaxf(s[j][2], s[j][3]));
        }
        mn0 = fmaxf(mn0, __shfl_xor_sync(0xffffffffu, mn0, 1));
        mn0 = fmaxf(mn0, __shfl_xor_sync(0xffffffffu, mn0, 2));
        mn1 = fmaxf(mn1, __shfl_xor_sync(0xffffffffu, mn1, 1));
        mn1 = fmaxf(mn1, __shfl_xor_sync(0xffffffffu, mn1, 2));
        float alpha0 = __expf(m0 - mn0);
        float alpha1 = __expf(m1 - mn1);
        m0 = mn0; m1 = mn1;
        float rs0 = 0.f, rs1 = 0.f;
        #pragma unroll
        for (int j = 0; j < 8; j++) {
            s[j][0] = __expf(s[j][0] - mn0);
            s[j][1] = __expf(s[j][1] - mn0);
            s[j][2] = __expf(s[j][2] - mn1);
            s[j][3] = __expf(s[j][3] - mn1);
            rs0 += s[j][0] + s[j][1];
            rs1 += s[j][2] + s[j][3];
        }
        l0 = l0 * alpha0 + rs0;
        l1 = l1 * alpha1 + rs1;
        #pragma unroll
        for (int j = 0; j < 8; j++) {
            o[j][0] *= alpha0; o[j][1] *= alpha0;
            o[j][2] *= alpha1; o[j][3] *= alpha1;
        }

        // ---- O += P @ V (3-pass) ----
        #pragma unroll
        for (int ks = 0; ks < 4; ks++) {
            uint32_t pa[4], pl[4];
            pa[0] = pack_bf16(s[2 * ks][0], s[2 * ks][1]);
            pa[1] = pack_bf16(s[2 * ks][2], s[2 * ks][3]);
            pa[2] = pack_bf16(s[2 * ks + 1][0], s[2 * ks + 1][1]);
            pa[3] = pack_bf16(s[2 * ks + 1][2], s[2 * ks + 1][3]);
            pl[0] = pack_bf16_lo(s[2 * ks][0], s[2 * ks][1], pa[0]);
            pl[1] = pack_bf16_lo(s[2 * ks][2], s[2 * ks][3], pa[1]);
            pl[2] = pack_bf16_lo(s[2 * ks + 1][0], s[2 * ks + 1][1], pa[2]);
            pl[3] = pack_bf16_lo(s[2 * ks + 1][2], s[2 * ks + 1][3], pa[3]);
            #pragma unroll
            for (int jp = 0; jp < 4; jp++) {
                uint32_t vh[2][2], vl[2][2];
                uint32_t va = bv + jp * 16 * AST + ks * 32;
                LDMATRIX_X4(vh[0][0], vh[0][1], vh[1][0], vh[1][1], va);
                LDMATRIX_X4(vl[0][0], vl[0][1], vl[1][0], vl[1][1], va + KSZ);
                #pragma unroll
                for (int q = 0; q < 2; q++) {
                    int j = 2 * jp + q;
                    MMA_BF16(o[j], pa, vh[q]);
                    MMA_BF16(o[j], pa, vl[q]);
                    MMA_BF16(o[j], pl, vh[q]);
                }
            }
        }
        __syncthreads();
    }

    // ---- finalize ----
    l0 += __shfl_xor_sync(0xffffffffu, l0, 1);
    l0 += __shfl_xor_sync(0xffffffffu, l0, 2);
    l1 += __shfl_xor_sync(0xffffffffu, l1, 1);
    l1 += __shfl_xor_sync(0xffffffffu, l1, 2);

    if (nsp == 1) {
        float inv0 = 1.f / l0, inv1 = 1.f / l1;
        #pragma unroll
        for (int j = 0; j < 8; j++) {
            int col = h * 64 + 8 * j + 2 * (l & 3);
            uint32_t hp, lp;
            split2(o[j][0] * inv0, o[j][1] * inv0, hp, lp);
            *(uint32_t*)(AOh + (size_t)row0g * D_DIM + col) = hp;
            *(uint32_t*)(AOl + (size_t)row0g * D_DIM + col) = lp;
            split2(o[j][2] * inv1, o[j][3] * inv1, hp, lp);
            *(uint32_t*)(AOh + (size_t)(row0g + 8) * D_DIM + col) = hp;
            *(uint32_t*)(AOl + (size_t)(row0g + 8) * D_DIM + col) = lp;
        }
    } else {
        float* po = Po + (size_t)pidx * 8192;
        float* pml = Pml + (size_t)pidx * 256;
        int r0 = 16 * w + (l >> 2);
        #pragma unroll
        for (int j = 0; j < 8; j++) {
            int c = 8 * j + 2 * (l & 3);
            float2 v0; v0.x = o[j][0]; v0.y = o[j][1];
            float2 v1; v1.x = o[j][2]; v1.y = o[j][3];
            *(float2*)(po + r0 * 64 + c) = v0;
            *(float2*)(po + (r0 + 8) * 64 + c) = v1;
        }
        if ((l & 3) == 0) {
            pml[r0 * 2] = m0; pml[r0 * 2 + 1] = l0;
            pml[(r0 + 8) * 2] = m1; pml[(r0 + 8) * 2 + 1] = l1;
        }
    }
}

// ---------------- split-K combine (qb >= 4) ----------------
__global__ void attn_combine(const float* __restrict__ Po, const float* __restrict__ Pml,
                             bf16* __restrict__ AOh, bf16* __restrict__ AOl) {
    int qb = 4 + (int)blockIdx.x;
    int h = blockIdx.y;
    int nsp = nsp_of(qb);
    int base = 0;
    for (int i = 0; i < qb; i++) base += nsp_of(i);
    int tid = threadIdx.x;
    int row = tid >> 1;
    int c0 = (tid & 1) * 32;

    float mi[8], li[8], wgt[8];
    float mg = -1e30f;
    for (int i = 0; i < nsp; i++) {
        const float* pml = Pml + (size_t)((base + i) * 8 + h) * 256;
        mi[i] = pml[row * 2];
        li[i] = pml[row * 2 + 1];
        mg = fmaxf(mg, mi[i]);
    }
    float L = 0.f;
    for (int i = 0; i < nsp; i++) { wgt[i] = __expf(mi[i] - mg); L += li[i] * wgt[i]; }
    float invL = 1.f / L;

    size_t orow = (size_t)(qb * 128 + row) * D_DIM + h * 64;
    for (int c = c0; c < c0 + 32; c += 2) {
        float x = 0.f, y = 0.f;
        for (int i = 0; i < nsp; i++) {
            const float* p = Po + (size_t)((base + i) * 8 + h) * 8192 + row * 64 + c;
            x += p[0] * wgt[i];
            y += p[1] * wgt[i];
        }
        x *= invL; y *= invL;
        uint32_t hp, lp;
        split2(x, y, hp, lp);
        *(uint32_t*)(AOh + orow + c) = hp;
        *(uint32_t*)(AOl + orow + c) = lp;
    }
}

// ---------------- launch ----------------
extern "C" void kernel_launch(void* const* d_in, const int* in_sizes, int n_in,
                              void* d_out, int out_size) {
    const float* x    = (const float*)d_in[0];
    const float* wqkv = (const float*)d_in[1];
    const float* bqkv = (const float*)d_in[2];
    const float* wout = (const float*)d_in[3];
    const float* bout = (const float*)d_in[4];
    const float* wff1 = (const float*)d_in[5];
    const float* bff1 = (const float*)d_in[6];
    const float* wff2 = (const float*)d_in[7];
    const float* bff2 = (const float*)d_in[8];
    const float* g1   = (const float*)d_in[9];
    const float* bt1  = (const float*)d_in[10];
    const float* g2   = (const float*)d_in[11];
    const float* bt2  = (const float*)d_in[12];
    float* out = (float*)d_out;

    bf16 *hh, *hl, *wqh, *wql, *woh, *wol, *w1h, *w1l, *w2h, *w2l;
    bf16 *qkh, *qkl, *vth, *vtl, *aoh, *aol, *h2h, *h2l, *ffh, *ffl;
    float *x1, *po, *pml;
    cudaGetSymbolAddress((void**)&hh,  g_h_hi);   cudaGetSymbolAddress((void**)&hl,  g_h_lo);
    cudaGetSymbolAddress((void**)&wqh, g_wqkvT_hi); cudaGetSymbolAddress((void**)&wql, g_wqkvT_lo);
    cudaGetSymbolAddress((void**)&woh, g_woutT_hi); cudaGetSymbolAddress((void**)&wol, g_woutT_lo);
    cudaGetSymbolAddress((void**)&w1h, g_wff1T_hi); cudaGetSymbolAddress((void**)&w1l, g_wff1T_lo);
    cudaGetSymbolAddress((void**)&w2h, g_wff2T_hi); cudaGetSymbolAddress((void**)&w2l, g_wff2T_lo);
    cudaGetSymbolAddress((void**)&qkh, g_qk_hi);  cudaGetSymbolAddress((void**)&qkl, g_qk_lo);
    cudaGetSymbolAddress((void**)&vth, g_vt_hi);  cudaGetSymbolAddress((void**)&vtl, g_vt_lo);
    cudaGetSymbolAddress((void**)&aoh, g_ao_hi);  cudaGetSymbolAddress((void**)&aol, g_ao_lo);
    cudaGetSymbolAddress((void**)&h2h, g_h2_hi);  cudaGetSymbolAddress((void**)&h2l, g_h2_lo);
    cudaGetSymbolAddress((void**)&ffh, g_ff_hi);  cudaGetSymbolAddress((void**)&ffl, g_ff_lo);
    cudaGetSymbolAddress((void**)&x1,  g_x1);
    cudaGetSymbolAddress((void**)&po,  g_po);
    cudaGetSymbolAddress((void**)&pml, g_pml);

    const int GS128 = 2 * (2 * 128 * 80 + 2 * 128 * 80);       // 81920 (2-stage)
    const int GS64  = 3 * (2 * 128 * 80 + 2 * 64 * 80);        // 92160 (3-stage)
    cudaFuncSetAttribute(gemm_cp<128, 512, 0, 2>, cudaFuncAttributeMaxDynamicSharedMemorySize, GS128);
    cudaFuncSetAttribute(gemm_cp<128, 512, 1, 2>, cudaFuncAttributeMaxDynamicSharedMemorySize, GS128);
    cudaFuncSetAttribute(gemm_cp<64, 512, 2, 3>,  cudaFuncAttributeMaxDynamicSharedMemorySize, GS64);
    cudaFuncSetAttribute(gemm_cp<64, 1024, 2, 3>, cudaFuncAttributeMaxDynamicSharedMemorySize, GS64);
    cudaFuncSetAttribute(attn_cp, cudaFuncAttributeMaxDynamicSharedMemorySize, ATT_SMEM);

    // 0) all weight preps in one launch
    wprep4<<<2048, 256>>>(wqkv, wqh, wql, wout, woh, wol, wff1, w1h, w1l, wff2, w2h, w2l);

    // 1) h = LN1(x) -> split
    ln_split<<<S_LEN, 256>>>(x, g1, bt1, hh, hl);
    // 2) qkv = h @ w_qkv + b_qkv -> qk split + vt split
    gemm_cp<128, 512, 0, 2><<<dim3(12, 32), 256, GS128>>>(hh, hl, wqh, wql, bqkv,
        nullptr, nullptr, qkh, qkl, vth, vtl, 1536);
    // 3) attention, split-K (max 8 tiles/split) -> ao split (+ partials)
    attn_cp<<<dim3(144, 8), 256, ATT_SMEM>>>(qkh, qkl, vth, vtl, aoh, aol, po, pml);
    attn_combine<<<dim3(28, 8), 256>>>(po, pml, aoh, aol);
    // 4) x1 = x + ao @ w_out + b_out  (fp32)
    gemm_cp<64, 512, 2, 3><<<dim3(8, 32), 256, GS64>>>(aoh, aol, woh, wol, bout,
        x, x1, nullptr, nullptr, nullptr, nullptr, 512);
    // 5) h2 = LN2(x1) -> split
    ln_split<<<S_LEN, 256>>>(x1, g2, bt2, h2h, h2l);
    // 6) ff = gelu(h2 @ w_ff1 + b_ff1) -> split
    gemm_cp<128, 512, 1, 2><<<dim3(8, 32), 256, GS128>>>(h2h, h2l, w1h, w1l, bff1,
        nullptr, nullptr, ffh, ffl, nullptr, nullptr, 1024);
    // 7) out = x1 + ff @ w_ff2 + b_ff2  (fp32)
    gemm_cp<64, 1024, 2, 3><<<dim3(8, 32), 256, GS64>>>(ffh, ffl, w2h, w2l, bff2,
        x1, out, nullptr, nullptr, nullptr, nullptr, 512);
}

// round 10
// speedup vs baseline: 1.1895x; 1.1895x over previous
#include <cuda_runtime.h>
#include <cuda_bf16.h>
#include <cuda_fp16.h>
#include <math.h>
#include <stdint.h>

typedef __nv_bfloat16 bf16;
typedef __half f16;

#define S_LEN 4096
#define D_DIM 512
#define FF_DIM 1024
#define EPS_LN 1e-5f

// ---------------- persistent scratch (no allocations) ----------------
__device__ bf16 g_h_hi [S_LEN * D_DIM],  g_h_lo [S_LEN * D_DIM];
__device__ bf16 g_wqkvT_hi[1536 * 512],  g_wqkvT_lo[1536 * 512];
__device__ f16  g_woutT[512 * 512];
__device__ f16  g_wff1T[1024 * 512];
__device__ f16  g_wff2T[512 * 1024];
__device__ bf16 g_qk_hi[S_LEN * 1024],   g_qk_lo[S_LEN * 1024];
__device__ f16  g_vt[512 * S_LEN];                    // [h*64+dh][seq], fp16
__device__ f16  g_ao_hi[S_LEN * D_DIM],  g_ao_lo[S_LEN * D_DIM];
__device__ f16  g_h2_hi[S_LEN * D_DIM],  g_h2_lo[S_LEN * D_DIM];
__device__ f16  g_ff_hi[S_LEN * FF_DIM], g_ff_lo[S_LEN * FF_DIM];
__device__ float g_x1[S_LEN * D_DIM];
__device__ float g_po[1152 * 128 * 64];
__device__ float g_pml[1152 * 256];

__device__ __forceinline__ uint32_t smem_u32(const void* p) {
    uint32_t a;
    asm("{ .reg .u64 t; cvta.to.shared.u64 t, %1; cvt.u32.u64 %0, t; }" : "=r"(a) : "l"(p));
    return a;
}

#define LDMATRIX_X4(r0, r1, r2, r3, a) \
    asm volatile("ldmatrix.sync.aligned.m8n8.x4.shared.b16 {%0,%1,%2,%3}, [%4];" \
        : "=r"(r0), "=r"(r1), "=r"(r2), "=r"(r3) : "r"(a))
#define MMA_BF16(d, a, b) \
    asm volatile("mma.sync.aligned.m16n8k16.row.col.f32.bf16.bf16.f32 " \
        "{%0,%1,%2,%3}, {%4,%5,%6,%7}, {%8,%9}, {%0,%1,%2,%3};" \
        : "+f"((d)[0]), "+f"((d)[1]), "+f"((d)[2]), "+f"((d)[3]) \
        : "r"((a)[0]), "r"((a)[1]), "r"((a)[2]), "r"((a)[3]), "r"((b)[0]), "r"((b)[1]))
#define MMA_F16(d, a, b) \
    asm volatile("mma.sync.aligned.m16n8k16.row.col.f32.f16.f16.f32 " \
        "{%0,%1,%2,%3}, {%4,%5,%6,%7}, {%8,%9}, {%0,%1,%2,%3};" \
        : "+f"((d)[0]), "+f"((d)[1]), "+f"((d)[2]), "+f"((d)[3]) \
        : "r"((a)[0]), "r"((a)[1]), "r"((a)[2]), "r"((a)[3]), "r"((b)[0]), "r"((b)[1]))

#define CP16(dst, src) asm volatile("cp.async.cg.shared.global [%0], [%1], 16;" :: "r"(dst), "l"(src))
#define CP_COMMIT()    asm volatile("cp.async.commit_group;")
#define CP_WAIT1()     asm volatile("cp.async.wait_group 1;" ::: "memory")
#define CP_WAIT0()     asm volatile("cp.async.wait_group 0;" ::: "memory")

__device__ __forceinline__ void split2b(float x, float y, uint32_t& hp, uint32_t& lp) {
    __nv_bfloat162 h = __floats2bfloat162_rn(x, y);
    float lx = x - __bfloat162float(__low2bfloat16(h));
    float ly = y - __bfloat162float(__high2bfloat16(h));
    __nv_bfloat162 l = __floats2bfloat162_rn(lx, ly);
    hp = *(uint32_t*)&h; lp = *(uint32_t*)&l;
}
__device__ __forceinline__ void split2h(float x, float y, uint32_t& hp, uint32_t& lp) {
    __half2 h = __floats2half2_rn(x, y);
    float lx = x - __half2float(__low2half(h));
    float ly = y - __half2float(__high2half(h));
    __half2 l = __floats2half2_rn(lx, ly);
    hp = *(uint32_t*)&h; lp = *(uint32_t*)&l;
}
__device__ __forceinline__ uint32_t pack_f16(float x, float y) {
    __half2 h = __floats2half2_rn(x, y);
    return *(uint32_t*)&h;
}

__device__ __forceinline__ int nsp_of(int qb) { return (2 * qb + 9) >> 3; }

// ---------------- merged weight prep ----------------
// wqkv -> bf16 hi/lo; wout/wff1/wff2 -> fp16 single
__global__ void wprep4(const float* __restrict__ s0, bf16* __restrict__ bh0, bf16* __restrict__ bl0,
                       const float* __restrict__ s1, f16* __restrict__ h1,
                       const float* __restrict__ s2, f16* __restrict__ h2,
                       const float* __restrict__ s3, f16* __restrict__ h3) {
    __shared__ float t[32][33];
    int b = blockIdx.x;
    const float* src; int K, N, nx, rb, mode;
    bf16 *dbh = nullptr, *dbl = nullptr; f16* dh = nullptr;
    if (b < 768)       { src = s0; dbh = bh0; dbl = bl0; K = 512;  N = 1536; nx = 48; rb = b;        mode = 0; }
    else if (b < 1024) { src = s1; dh = h1; K = 512;  N = 512;  nx = 16; rb = b - 768;  mode = 1; }
    else if (b < 1536) { src = s2; dh = h2; K = 512;  N = 1024; nx = 32; rb = b - 1024; mode = 1; }
    else               { src = s3; dh = h3; K = 1024; N = 512;  nx = 16; rb = b - 1536; mode = 1; }
    int n0 = (rb % nx) * 32, k0 = (rb / nx) * 32;
    int tx = threadIdx.x & 31, ty = threadIdx.x >> 5;
    #pragma unroll
    for (int i = 0; i < 32; i += 8)
        t[ty + i][tx] = src[(size_t)(k0 + ty + i) * N + n0 + tx];
    __syncthreads();
    #pragma unroll
    for (int i = 0; i < 32; i += 8) {
        float v = t[tx][ty + i];
        size_t idx = (size_t)(n0 + ty + i) * K + k0 + tx;
        if (mode == 0) {
            bf16 h = __float2bfloat16(v);
            bf16 l = __float2bfloat16(v - __bfloat162float(h));
            dbh[idx] = h; dbl[idx] = l;
        } else {
            dh[idx] = __float2half(v);
        }
    }
}

// ---------------- LayerNorm -> split (bf16 or fp16) ----------------
template <int F16OUT>
__global__ void ln_split(const float* __restrict__ x, const float* __restrict__ g,
                         const float* __restrict__ b, void* __restrict__ ohv,
                         void* __restrict__ olv) {
    __shared__ float red[32];
    __shared__ float s_mean, s_rstd;
    int row = blockIdx.x;
    int tid = threadIdx.x;
    float2 v = *(const float2*)(x + (size_t)row * D_DIM + tid * 2);

    float sum = v.x + v.y;
    #pragma unroll
    for (int o = 16; o > 0; o >>= 1) sum += __shfl_down_sync(0xffffffffu, sum, o);
    if ((tid & 31) == 0) red[tid >> 5] = sum;
    __syncthreads();
    if (tid < 32) {
        float t = (tid < 8) ? red[tid] : 0.f;
        #pragma unroll
        for (int o = 4; o > 0; o >>= 1) t += __shfl_down_sync(0xffffffffu, t, o);
        if (tid == 0) s_mean = t * (1.f / D_DIM);
    }
    __syncthreads();
    float mean = s_mean;
    float d0 = v.x - mean, d1 = v.y - mean;

    float vs = d0 * d0 + d1 * d1;
    #pragma unroll
    for (int o = 16; o > 0; o >>= 1) vs += __shfl_down_sync(0xffffffffu, vs, o);
    if ((tid & 31) == 0) red[tid >> 5] = vs;
    __syncthreads();
    if (tid < 32) {
        float t = (tid < 8) ? red[tid] : 0.f;
        #pragma unroll
        for (int o = 4; o > 0; o >>= 1) t += __shfl_down_sync(0xffffffffu, t, o);
        if (tid == 0) s_rstd = rsqrtf(t * (1.f / D_DIM) + EPS_LN);
    }
    __syncthreads();
    float rstd = s_rstd;

    int c = tid * 2;
    float2 gg = *(const float2*)(g + c);
    float2 bb = *(const float2*)(b + c);
    float ox = d0 * rstd * gg.x + bb.x;
    float oy = d1 * rstd * gg.y + bb.y;
    uint32_t hp, lp;
    if (F16OUT) split2h(ox, oy, hp, lp);
    else        split2b(ox, oy, hp, lp);
    *((uint32_t*)ohv + (size_t)row * (D_DIM / 2) + tid) = hp;
    *((uint32_t*)olv + (size_t)row * (D_DIM / 2) + tid) = lp;
}

// ---------------- bf16 3-pass GEMM (QKV only) ----------------
__global__ void __launch_bounds__(256, 2)
gemm_qkv(const bf16* __restrict__ Ah, const bf16* __restrict__ Al,
         const bf16* __restrict__ Bh, const bf16* __restrict__ Bl,
         const float* __restrict__ bias,
         bf16* __restrict__ Ch, bf16* __restrict__ Cl,
         f16* __restrict__ Vt) {
    constexpr int BN = 128, K_TOT = 512, N = 1536;
    constexpr int A_SZ = 128 * 80;
    constexpr int B_SZ = BN * 80;
    constexpr int B_OFF = 2 * A_SZ;
    constexpr int BUF = 2 * A_SZ + 2 * B_SZ;
    constexpr int NS = K_TOT / 32;

    extern __shared__ __align__(16) char smx[];
    const uint32_t sbase = smem_u32(smx);

    int tid = threadIdx.x;
    int wid = tid >> 5;
    int l = tid & 31;
    int bm = blockIdx.y * 128, bn = blockIdx.x * BN;
    int warp_m = wid / 4, warp_n = wid % 4;   // 2x4 warps, WM=64

    float d[4][4][4];
    #pragma unroll
    for (int i = 0; i < 4; i++)
        #pragma unroll
        for (int j = 0; j < 4; j++)
            #pragma unroll
            for (int k = 0; k < 4; k++) d[i][j][k] = 0.f;

    int lb = l & 15;
    uint32_t a_rel = (uint32_t)(warp_m * 64 + lb) * 80 + (uint32_t)(l >> 4) * 16;
    uint32_t b_rel = B_OFF + (uint32_t)(warp_n * 32 + (l >> 4) * 8 + (l & 7)) * 80 +
                     (uint32_t)((l >> 3) & 1) * 16;

    int a_cc = tid & 3, a_row = tid >> 2;

    auto issue = [&](int s) {
        int k0 = s * 32;
        uint32_t bufb = sbase + (uint32_t)((s & 1) * BUF);
        #pragma unroll
        for (int t = 0; t < 2; t++) {
            int row = a_row + t * 64;
            size_t so = (size_t)(bm + row) * K_TOT + k0 + a_cc * 8;
            uint32_t dst = bufb + (uint32_t)(row * 80 + a_cc * 16);
            CP16(dst, Ah + so);
            CP16(dst + A_SZ, Al + so);
        }
        #pragma unroll
        for (int t = 0; t < 2; t++) {
            int c = tid + t * 256;
            int cc = c & 3, row = c >> 2;
            size_t so = (size_t)(bn + row) * K_TOT + k0 + cc * 8;
            uint32_t dst = bufb + B_OFF + (uint32_t)(row * 80 + cc * 16);
            CP16(dst, Bh + so);
            CP16(dst + B_SZ, Bl + so);
        }
    };

    issue(0); CP_COMMIT();

    for (int s = 0; s < NS; s++) {
        if (s + 1 < NS) { issue(s + 1); CP_COMMIT(); CP_WAIT1(); }
        else CP_WAIT0();
        __syncthreads();

        uint32_t cb = sbase + (uint32_t)((s & 1) * BUF);
        #pragma unroll
        for (int ks = 0; ks < 2; ks++) {
            uint32_t bh[4][2], blo[4][2];
            #pragma unroll
            for (int pj = 0; pj < 2; pj++) {
                uint32_t ba = cb + b_rel + pj * 16 * 80 + ks * 32;
                LDMATRIX_X4(bh[2 * pj][0], bh[2 * pj][1], bh[2 * pj + 1][0], bh[2 * pj + 1][1], ba);
                LDMATRIX_X4(blo[2 * pj][0], blo[2 * pj][1], blo[2 * pj + 1][0], blo[2 * pj + 1][1], ba + B_SZ);
            }
            #pragma unroll
            for (int mi = 0; mi < 4; mi++) {
                uint32_t ah[4], al[4];
                uint32_t aa = cb + a_rel + mi * 16 * 80 + ks * 32;
                LDMATRIX_X4(ah[0], ah[1], ah[2], ah[3], aa);
                LDMATRIX_X4(al[0], al[1], al[2], al[3], aa + A_SZ);
                #pragma unroll
                for (int nj = 0; nj < 4; nj++) {
                    MMA_BF16(d[mi][nj], ah, bh[nj]);
                    MMA_BF16(d[mi][nj], ah, blo[nj]);
                    MMA_BF16(d[mi][nj], al, bh[nj]);
                }
            }
        }
        __syncthreads();
    }

    #pragma unroll
    for (int mi = 0; mi < 4; mi++) {
        int row0 = bm + warp_m * 64 + mi * 16 + (l >> 2);
        #pragma unroll
        for (int nj = 0; nj < 4; nj++) {
            int col = bn + warp_n * 32 + nj * 8 + (l & 3) * 2;
            float2 bb = *(const float2*)(bias + col);
            #pragma unroll
            for (int half = 0; half < 2; half++) {
                int row = row0 + half * 8;
                float vx = d[mi][nj][half * 2 + 0] + bb.x;
                float vy = d[mi][nj][half * 2 + 1] + bb.y;
                if (col < 1024) {
                    uint32_t hp, lp;
                    split2b(vx, vy, hp, lp);
                    *(uint32_t*)(Ch + (size_t)row * 1024 + col) = hp;
                    *(uint32_t*)(Cl + (size_t)row * 1024 + col) = lp;
                } else {
                    int hc = col - 1024;
                    size_t i0 = (size_t)hc * S_LEN + row;
                    Vt[i0] = __float2half(vx);
                    Vt[i0 + S_LEN] = __float2half(vy);
                }
            }
        }
    }
}

// ---------------- fp16 2-pass GEMM (A split hi/lo, B single) ----------------
// EPI: 1 = bias+GELU -> fp16 split store; 2 = bias+residual -> fp32
template <int BN, int K_TOT, int EPI, int STAGES>
__global__ void __launch_bounds__(256, 2)
gemm2(const f16* __restrict__ Ah, const f16* __restrict__ Al,
      const f16* __restrict__ B,
      const float* __restrict__ bias, const float* __restrict__ res,
      float* __restrict__ Cf, f16* __restrict__ Ch, f16* __restrict__ Cl, int N) {
    constexpr int WARPS_N = BN / 32;
    constexpr int WARPS_M = 8 / WARPS_N;
    constexpr int WM = 128 / WARPS_M;
    constexpr int MI = WM / 16;
    constexpr int A_SZ = 128 * 80;
    constexpr int B_SZ = BN * 80;
    constexpr int B_OFF = 2 * A_SZ;
    constexpr int BUF = 2 * A_SZ + B_SZ;
    constexpr int NS = K_TOT / 32;

    extern __shared__ __align__(16) char smx[];
    const uint32_t sbase = smem_u32(smx);

    int tid = threadIdx.x;
    int wid = tid >> 5;
    int l = tid & 31;
    int bm = blockIdx.y * 128, bn = blockIdx.x * BN;
    int warp_m = wid / WARPS_N, warp_n = wid % WARPS_N;

    float d[MI][4][4];
    #pragma unroll
    for (int i = 0; i < MI; i++)
        #pragma unroll
        for (int j = 0; j < 4; j++)
            #pragma unroll
            for (int k = 0; k < 4; k++) d[i][j][k] = 0.f;

    int lb = l & 15;
    uint32_t a_rel = (uint32_t)(warp_m * WM + lb) * 80 + (uint32_t)(l >> 4) * 16;
    uint32_t b_rel = B_OFF + (uint32_t)(warp_n * 32 + (l >> 4) * 8 + (l & 7)) * 80 +
                     (uint32_t)((l >> 3) & 1) * 16;

    int a_cc = tid & 3, a_row = tid >> 2;
    constexpr int BCH = BN * 4;

    auto issue = [&](int s) {
        int k0 = s * 32;
        uint32_t bufb = sbase + (uint32_t)((s % STAGES) * BUF);
        #pragma unroll
        for (int t = 0; t < 2; t++) {
            int row = a_row + t * 64;
            size_t so = (size_t)(bm + row) * K_TOT + k0 + a_cc * 8;
            uint32_t dst = bufb + (uint32_t)(row * 80 + a_cc * 16);
            CP16(dst, Ah + so);
            CP16(dst + A_SZ, Al + so);
        }
        #pragma unroll
        for (int t = 0; t < BCH / 256; t++) {
            int c = tid + t * 256;
            int cc = c & 3, row = c >> 2;
            size_t so = (size_t)(bn + row) * K_TOT + k0 + cc * 8;
            CP16(bufb + B_OFF + (uint32_t)(row * 80 + cc * 16), B + so);
        }
    };

    auto compute = [&](int s) {
        uint32_t cb = sbase + (uint32_t)((s % STAGES) * BUF);
        #pragma unroll
        for (int ks = 0; ks < 2; ks++) {
            uint32_t bh[4][2];
            #pragma unroll
            for (int pj = 0; pj < 2; pj++) {
                uint32_t ba = cb + b_rel + pj * 16 * 80 + ks * 32;
                LDMATRIX_X4(bh[2 * pj][0], bh[2 * pj][1], bh[2 * pj + 1][0], bh[2 * pj + 1][1], ba);
            }
            #pragma unroll
            for (int mi = 0; mi < MI; mi++) {
                uint32_t ah[4], al[4];
                uint32_t aa = cb + a_rel + mi * 16 * 80 + ks * 32;
                LDMATRIX_X4(ah[0], ah[1], ah[2], ah[3], aa);
                LDMATRIX_X4(al[0], al[1], al[2], al[3], aa + A_SZ);
                #pragma unroll
                for (int nj = 0; nj < 4; nj++) {
                    MMA_F16(d[mi][nj], ah, bh[nj]);
                    MMA_F16(d[mi][nj], al, bh[nj]);
                }
            }
        }
    };

    if (STAGES == 3) {
        issue(0); CP_COMMIT();
        issue(1); CP_COMMIT();
        for (int s = 0; s < NS; s++) {
            if (s == NS - 1) CP_WAIT0(); else CP_WAIT1();
            __syncthreads();
            compute(s);
            if (s + 2 < NS) { issue(s + 2); CP_COMMIT(); }
        }
    } else {
        issue(0); CP_COMMIT();
        for (int s = 0; s < NS; s++) {
            if (s + 1 < NS) { issue(s + 1); CP_COMMIT(); CP_WAIT1(); }
            else CP_WAIT0();
            __syncthreads();
            compute(s);
            __syncthreads();
        }
    }

    #pragma unroll
    for (int mi = 0; mi < MI; mi++) {
        int row0 = bm + warp_m * WM + mi * 16 + (l >> 2);
        #pragma unroll
        for (int nj = 0; nj < 4; nj++) {
            int col = bn + warp_n * 32 + nj * 8 + (l & 3) * 2;
            float2 bb = *(const float2*)(bias + col);
            #pragma unroll
            for (int half = 0; half < 2; half++) {
                int row = row0 + half * 8;
                float vx = d[mi][nj][half * 2 + 0] + bb.x;
                float vy = d[mi][nj][half * 2 + 1] + bb.y;
                if (EPI == 1) {
                    vx = 0.5f * vx * (1.f + erff(vx * 0.70710678118654752f));
                    vy = 0.5f * vy * (1.f + erff(vy * 0.70710678118654752f));
                    uint32_t hp, lp;
                    split2h(vx, vy, hp, lp);
                    *(uint32_t*)(Ch + (size_t)row * N + col) = hp;
                    *(uint32_t*)(Cl + (size_t)row * N + col) = lp;
                } else {
                    float2 rr = *(const float2*)(res + (size_t)row * N + col);
                    float2 o2; o2.x = vx + rr.x; o2.y = vy + rr.y;
                    *(float2*)(Cf + (size_t)row * N + col) = o2;
                }
            }
        }
    }
}

// ---------------- flash attention: QK bf16 3-pass, PV fp16 1-pass, split-K ----------------
#define AST 144
#define QSZ (128 * AST)
#define KSZ (64 * AST)
#define KVBUF (3 * KSZ)
#define KV0 (2 * QSZ)
#define ATT_SMEM (KV0 + 2 * KVBUF)

__global__ void __launch_bounds__(256, 2)
attn_cp(const bf16* __restrict__ QKh, const bf16* __restrict__ QKl,
        const f16* __restrict__ Vt,
        f16* __restrict__ AOh, f16* __restrict__ AOl,
        float* __restrict__ Po, float* __restrict__ Pml) {
    extern __shared__ char sm[];
    const uint32_t sbase = smem_u32(sm);

    int gx = (int)gridDim.x - 1 - (int)blockIdx.x;
    int qb = 0, acc = 0;
    while (acc + nsp_of(qb) <= gx) { acc += nsp_of(qb); qb++; }
    int sp = gx - acc;
    int nsp = nsp_of(qb);
    int total = 2 * qb + 2;
    int chunk = (total + nsp - 1) / nsp;
    int kb_begin = sp * chunk;
    int kb_end = min(total, kb_begin + chunk);
    int pidx = gx * 8 + (int)blockIdx.y;

    int h = blockIdx.y;
    int tid = threadIdx.x;
    int w = tid >> 5;
    int l = tid & 31;
    int lb = l & 15;

    int q_cc = tid & 7, q_row = tid >> 3;
    auto issueQ = [&]() {
        #pragma unroll
        for (int t = 0; t < 4; t++) {
            int row = q_row + t * 32;
            size_t so = (size_t)(qb * 128 + row) * 1024 + h * 64 + q_cc * 8;
            uint32_t dst = sbase + (uint32_t)(row * AST + q_cc * 16);
            CP16(dst, QKh + so);
            CP16(dst + QSZ, QKl + so);
        }
    };
    auto issueKV = [&](int kb) {
        uint32_t base = sbase + KV0 + (uint32_t)((kb & 1) * KVBUF);
        #pragma unroll
        for (int t = 0; t < 2; t++) {
            int row = q_row + t * 32;
            uint32_t doff = (uint32_t)(row * AST + q_cc * 16);
            size_t sk = (size_t)(kb * 64 + row) * 1024 + 512 + h * 64 + q_cc * 8;
            CP16(base + doff, QKh + sk);
            CP16(base + KSZ + doff, QKl + sk);
            size_t sv = (size_t)(h * 64 + row) * S_LEN + kb * 64 + q_cc * 8;
            CP16(base + 2 * KSZ + doff, Vt + sv);
        }
    };

    issueQ();
    issueKV(kb_begin); CP_COMMIT();

    float o[8][4];
    #pragma unroll
    for (int j = 0; j < 8; j++)
        #pragma unroll
        for (int k = 0; k < 4; k++) o[j][k] = 0.f;
    float m0 = -1e30f, m1 = -1e30f, l0 = 0.f, l1 = 0.f;

    uint32_t aq = sbase + (uint32_t)((16 * w + lb) * AST) + (uint32_t)(l >> 4) * 16;
    uint32_t kv_rel = (uint32_t)(((l >> 4) * 8 + (l & 7)) * AST) + (uint32_t)((l >> 3) & 1) * 16;

    int row0g = qb * 128 + 16 * w + (l >> 2);

    for (int kb = kb_begin; kb < kb_end; kb++) {
        if (kb + 1 < kb_end) { issueKV(kb + 1); CP_COMMIT(); CP_WAIT1(); }
        else CP_WAIT0();
        __syncthreads();

        uint32_t kvb = sbase + KV0 + (uint32_t)((kb & 1) * KVBUF);
        uint32_t bk = kvb + kv_rel;
        uint32_t bv = kvb + 2 * KSZ + kv_rel;

        // ---- S = Q K^T (bf16 3-pass) ----
        float s[8][4];
        #pragma unroll
        for (int j = 0; j < 8; j++)
            #pragma unroll
            for (int k = 0; k < 4; k++) s[j][k] = 0.f;
        #pragma unroll
        for (int ks = 0; ks < 4; ks++) {
            uint32_t ah[4], al[4];
            LDMATRIX_X4(ah[0], ah[1], ah[2], ah[3], aq + ks * 32);
            LDMATRIX_X4(al[0], al[1], al[2], al[3], aq + ks * 32 + QSZ);
            #pragma unroll
            for (int jp = 0; jp < 4; jp++) {
                uint32_t bh[2][2], blo[2][2];
                uint32_t ba = bk + jp * 16 * AST + ks * 32;
                LDMATRIX_X4(bh[0][0], bh[0][1], bh[1][0], bh[1][1], ba);
                LDMATRIX_X4(blo[0][0], blo[0][1], blo[1][0], blo[1][1], ba + KSZ);
                #pragma unroll
                for (int q = 0; q < 2; q++) {
                    int j = 2 * jp + q;
                    MMA_BF16(s[j], ah, bh[q]);
                    MMA_BF16(s[j], ah, blo[q]);
                    MMA_BF16(s[j], al, bh[q]);
                }
            }
        }

        // ---- scale + causal mask ----
        int cbase = kb * 64 + 2 * (l & 3);
        bool need_mask = (kb >= 2 * qb);
        #pragma unroll
        for (int j = 0; j < 8; j++) {
            #pragma unroll
            for (int k = 0; k < 4; k++) s[j][k] *= 0.125f;
            if (need_mask) {
                int c0 = cbase + 8 * j;
                if (c0 > row0g)     s[j][0] = -1e30f;
                if (c0 + 1 > row0g) s[j][1] = -1e30f;
                if (c0 > row0g + 8)     s[j][2] = -1e30f;
                if (c0 + 1 > row0g + 8) s[j][3] = -1e30f;
            }
        }

        // ---- online softmax ----
        float mn0 = m0, mn1 = m1;
        #pragma unroll
        for (int j = 0; j < 8; j++) {
            mn0 = fmaxf(mn0, fmaxf(s[j][0], s[j][1]));
            mn1 = fmaxf(mn1, fmaxf(s[j][2], s[j][3]));
        }
        mn0 = fmaxf(mn0, __shfl_xor_sync(0xffffffffu, mn0, 1));
        mn0 = fmaxf(mn0, __shfl_xor_sync(0xffffffffu, mn0, 2));
        mn1 = fmaxf(mn1, __shfl_xor_sync(0xffffffffu, mn1, 1));
        mn1 = fmaxf(mn1, __shfl_xor_sync(0xffffffffu, mn1, 2));
        float alpha0 = __expf(m0 - mn0);
        float alpha1 = __expf(m1 - mn1);
        m0 = mn0; m1 = mn1;
        float rs0 = 0.f, rs1 = 0.f;
        #pragma unroll
        for (int j = 0; j < 8; j++) {
            s[j][0] = __expf(s[j][0] - mn0);
            s[j][1] = __expf(s[j][1] - mn0);
            s[j][2] = __expf(s[j][2] - mn1);
            s[j][3] = __expf(s[j][3] - mn1);
            rs0 += s[j][0] + s[j][1];
            rs1 += s[j][2] + s[j][3];
        }
        l0 = l0 * alpha0 + rs0;
        l1 = l1 * alpha1 + rs1;
        #pragma unroll
        for (int j = 0; j < 8; j++) {
            o[j][0] *= alpha0; o[j][1] *= alpha0;
            o[j][2] *= alpha1; o[j][3] *= alpha1;
        }

        // ---- O += P @ V (fp16 single-pass) ----
        #pragma unroll
        for (int ks = 0; ks < 4; ks++) {
            uint32_t pa[4];
            pa[0] = pack_f16(s[2 * ks][0], s[2 * ks][1]);
            pa[1] = pack_f16(s[2 * ks][2], s[2 * ks][3]);
            pa[2] = pack_f16(s[2 * ks + 1][0], s[2 * ks + 1][1]);
            pa[3] = pack_f16(s[2 * ks + 1][2], s[2 * ks + 1][3]);
            #pragma unroll
            for (int jp = 0; jp < 4; jp++) {
                uint32_t vh[2][2];
                uint32_t va = bv + jp * 16 * AST + ks * 32;
                LDMATRIX_X4(vh[0][0], vh[0][1], vh[1][0], vh[1][1], va);
                MMA_F16(o[2 * jp], pa, vh[0]);
                MMA_F16(o[2 * jp + 1], pa, vh[1]);
            }
        }
        __syncthreads();
    }

    // ---- finalize ----
    l0 += __shfl_xor_sync(0xffffffffu, l0, 1);
    l0 += __shfl_xor_sync(0xffffffffu, l0, 2);
    l1 += __shfl_xor_sync(0xffffffffu, l1, 1);
    l1 += __shfl_xor_sync(0xffffffffu, l1, 2);

    if (nsp == 1) {
        float inv0 = 1.f / l0, inv1 = 1.f / l1;
        #pragma unroll
        for (int j = 0; j < 8; j++) {
            int col = h * 64 + 8 * j + 2 * (l & 3);
            uint32_t hp, lp;
            split2h(o[j][0] * inv0, o[j][1] * inv0, hp, lp);
            *(uint32_t*)(AOh + (size_t)row0g * D_DIM + col) = hp;
            *(uint32_t*)(AOl + (size_t)row0g * D_DIM + col) = lp;
            split2h(o[j][2] * inv1, o[j][3] * inv1, hp, lp);
            *(uint32_t*)(AOh + (size_t)(row0g + 8) * D_DIM + col) = hp;
            *(uint32_t*)(AOl + (size_t)(row0g + 8) * D_DIM + col) = lp;
        }
    } else {
        float* po = Po + (size_t)pidx * 8192;
        float* pml = Pml + (size_t)pidx * 256;
        int r0 = 16 * w + (l >> 2);
        #pragma unroll
        for (int j = 0; j < 8; j++) {
            int c = 8 * j + 2 * (l & 3);
            float2 v0; v0.x = o[j][0]; v0.y = o[j][1];
            float2 v1; v1.x = o[j][2]; v1.y = o[j][3];
            *(float2*)(po + r0 * 64 + c) = v0;
            *(float2*)(po + (r0 + 8) * 64 + c) = v1;
        }
        if ((l & 3) == 0) {
            pml[r0 * 2] = m0; pml[r0 * 2 + 1] = l0;
            pml[(r0 + 8) * 2] = m1; pml[(r0 + 8) * 2 + 1] = l1;
        }
    }
}

// ---------------- split-K combine (qb >= 4) ----------------
__global__ void attn_combine(const float* __restrict__ Po, const float* __restrict__ Pml,
                             f16* __restrict__ AOh, f16* __restrict__ AOl) {
    int qb = 4 + (int)blockIdx.x;
    int h = blockIdx.y;
    int nsp = nsp_of(qb);
    int base = 0;
    for (int i = 0; i < qb; i++) base += nsp_of(i);
    int tid = threadIdx.x;
    int row = tid >> 1;
    int c0 = (tid & 1) * 32;

    float mi[8], li[8], wgt[8];
    float mg = -1e30f;
    for (int i = 0; i < nsp; i++) {
        const float* pml = Pml + (size_t)((base + i) * 8 + h) * 256;
        mi[i] = pml[row * 2];
        li[i] = pml[row * 2 + 1];
        mg = fmaxf(mg, mi[i]);
    }
    float L = 0.f;
    for (int i = 0; i < nsp; i++) { wgt[i] = __expf(mi[i] - mg); L += li[i] * wgt[i]; }
    float invL = 1.f / L;

    size_t orow = (size_t)(qb * 128 + row) * D_DIM + h * 64;
    for (int c = c0; c < c0 + 32; c += 2) {
        float x = 0.f, y = 0.f;
        for (int i = 0; i < nsp; i++) {
            const float* p = Po + (size_t)((base + i) * 8 + h) * 8192 + row * 64 + c;
            x += p[0] * wgt[i];
            y += p[1] * wgt[i];
        }
        x *= invL; y *= invL;
        uint32_t hp, lp;
        split2h(x, y, hp, lp);
        *(uint32_t*)(AOh + orow + c) = hp;
        *(uint32_t*)(AOl + orow + c) = lp;
    }
}

// ---------------- launch ----------------
extern "C" void kernel_launch(void* const* d_in, const int* in_sizes, int n_in,
                              void* d_out, int out_size) {
    const float* x    = (const float*)d_in[0];
    const float* wqkv = (const float*)d_in[1];
    const float* bqkv = (const float*)d_in[2];
    const float* wout = (const float*)d_in[3];
    const float* bout = (const float*)d_in[4];
    const float* wff1 = (const float*)d_in[5];
    const float* bff1 = (const float*)d_in[6];
    const float* wff2 = (const float*)d_in[7];
    const float* bff2 = (const float*)d_in[8];
    const float* g1   = (const float*)d_in[9];
    const float* bt1  = (const float*)d_in[10];
    const float* g2   = (const float*)d_in[11];
    const float* bt2  = (const float*)d_in[12];
    float* out = (float*)d_out;

    bf16 *hh, *hl, *wqh, *wql, *qkh, *qkl;
    f16 *woT, *w1T, *w2T, *vt, *aoh, *aol, *h2h, *h2l, *ffh, *ffl;
    float *x1, *po, *pml;
    cudaGetSymbolAddress((void**)&hh,  g_h_hi);   cudaGetSymbolAddress((void**)&hl,  g_h_lo);
    cudaGetSymbolAddress((void**)&wqh, g_wqkvT_hi); cudaGetSymbolAddress((void**)&wql, g_wqkvT_lo);
    cudaGetSymbolAddress((void**)&woT, g_woutT);
    cudaGetSymbolAddress((void**)&w1T, g_wff1T);
    cudaGetSymbolAddress((void**)&w2T, g_wff2T);
    cudaGetSymbolAddress((void**)&qkh, g_qk_hi);  cudaGetSymbolAddress((void**)&qkl, g_qk_lo);
    cudaGetSymbolAddress((void**)&vt,  g_vt);
    cudaGetSymbolAddress((void**)&aoh, g_ao_hi);  cudaGetSymbolAddress((void**)&aol, g_ao_lo);
    cudaGetSymbolAddress((void**)&h2h, g_h2_hi);  cudaGetSymbolAddress((void**)&h2l, g_h2_lo);
    cudaGetSymbolAddress((void**)&ffh, g_ff_hi);  cudaGetSymbolAddress((void**)&ffl, g_ff_lo);
    cudaGetSymbolAddress((void**)&x1,  g_x1);
    cudaGetSymbolAddress((void**)&po,  g_po);
    cudaGetSymbolAddress((void**)&pml, g_pml);

    const int GSQKV = 2 * (2 * 128 * 80 + 2 * 128 * 80);        // 81920
    const int GS2_128 = 2 * (2 * 128 * 80 + 128 * 80);          // 61440 (ff1, 2-stage)
    const int GS2_64  = 3 * (2 * 128 * 80 + 64 * 80);           // 76800 (out/ff2, 3-stage)
    cudaFuncSetAttribute(gemm_qkv, cudaFuncAttributeMaxDynamicSharedMemorySize, GSQKV);
    cudaFuncSetAttribute(gemm2<128, 512, 1, 2>, cudaFuncAttributeMaxDynamicSharedMemorySize, GS2_128);
    cudaFuncSetAttribute(gemm2<64, 512, 2, 3>,  cudaFuncAttributeMaxDynamicSharedMemorySize, GS2_64);
    cudaFuncSetAttribute(gemm2<64, 1024, 2, 3>, cudaFuncAttributeMaxDynamicSharedMemorySize, GS2_64);
    cudaFuncSetAttribute(attn_cp, cudaFuncAttributeMaxDynamicSharedMemorySize, ATT_SMEM);

    // 0) weight prep
    wprep4<<<2048, 256>>>(wqkv, wqh, wql, wout, woT, wff1, w1T, wff2, w2T);
    // 1) h = LN1(x) -> bf16 split
    ln_split<0><<<S_LEN, 256>>>(x, g1, bt1, hh, hl);
    // 2) qkv (bf16 3-pass) -> qk bf16 split + vt fp16
    gemm_qkv<<<dim3(12, 32), 256, GSQKV>>>(hh, hl, wqh, wql, bqkv, qkh, qkl, vt);
    // 3) attention (QK bf16 3-pass, PV fp16 1-pass) -> ao fp16 split
    attn_cp<<<dim3(144, 8), 256, ATT_SMEM>>>(qkh, qkl, vt, aoh, aol, po, pml);
    attn_combine<<<dim3(28, 8), 256>>>(po, pml, aoh, aol);
    // 4) x1 = x + ao @ w_out + b_out  (fp16 2-pass)
    gemm2<64, 512, 2, 3><<<dim3(8, 32), 256, GS2_64>>>(aoh, aol, woT, bout, x, x1,
        nullptr, nullptr, 512);
    // 5) h2 = LN2(x1) -> fp16 split
    ln_split<1><<<S_LEN, 256>>>(x1, g2, bt2, h2h, h2l);
    // 6) ff = gelu(h2 @ w_ff1 + b_ff1)  (fp16 2-pass) -> fp16 split
    gemm2<128, 512, 1, 2><<<dim3(8, 32), 256, GS2_128>>>(h2h, h2l, w1T, bff1, nullptr,
        nullptr, ffh, ffl, 1024);
    // 7) out = x1 + ff @ w_ff2 + b_ff2  (fp16 2-pass)
    gemm2<64, 1024, 2, 3><<<dim3(8, 32), 256, GS2_64>>>(ffh, ffl, w2T, bff2, x1, out,
        nullptr, nullptr, 512);
}

// round 12
// speedup vs baseline: 1.3307x; 1.1187x over previous
#include <cuda_runtime.h>
#include <cuda_bf16.h>
#include <cuda_fp16.h>
#include <math.h>
#include <stdint.h>

typedef __half f16;

#define S_LEN 4096
#define D_DIM 512
#define FF_DIM 1024
#define EPS_LN 1e-5f

// ---------------- persistent scratch (no allocations) ----------------
__device__ f16  g_h_hi [S_LEN * D_DIM],  g_h_lo [S_LEN * D_DIM];
__device__ f16  g_wqkvT[1536 * 512];
__device__ f16  g_woutT[512 * 512];
__device__ f16  g_wff1T[1024 * 512];
__device__ f16  g_wff2T[512 * 1024];
__device__ f16  g_qk_hi[S_LEN * 1024],   g_qk_lo[S_LEN * 1024];  // lo used for Q only
__device__ f16  g_vt[512 * S_LEN];                    // [h*64+dh][seq]
__device__ f16  g_ao_hi[S_LEN * D_DIM],  g_ao_lo[S_LEN * D_DIM];
__device__ f16  g_h2_hi[S_LEN * D_DIM],  g_h2_lo[S_LEN * D_DIM];
__device__ f16  g_ff_hi[S_LEN * FF_DIM], g_ff_lo[S_LEN * FF_DIM];
__device__ float g_x1[S_LEN * D_DIM];
__device__ float g_po[1152 * 128 * 64];
__device__ float g_pml[1152 * 256];

__device__ __forceinline__ uint32_t smem_u32(const void* p) {
    uint32_t a;
    asm("{ .reg .u64 t; cvta.to.shared.u64 t, %1; cvt.u32.u64 %0, t; }" : "=r"(a) : "l"(p));
    return a;
}

#define LDMATRIX_X4(r0, r1, r2, r3, a) \
    asm volatile("ldmatrix.sync.aligned.m8n8.x4.shared.b16 {%0,%1,%2,%3}, [%4];" \
        : "=r"(r0), "=r"(r1), "=r"(r2), "=r"(r3) : "r"(a))
#define MMA_F16(d, a, b) \
    asm volatile("mma.sync.aligned.m16n8k16.row.col.f32.f16.f16.f32 " \
        "{%0,%1,%2,%3}, {%4,%5,%6,%7}, {%8,%9}, {%0,%1,%2,%3};" \
        : "+f"((d)[0]), "+f"((d)[1]), "+f"((d)[2]), "+f"((d)[3]) \
        : "r"((a)[0]), "r"((a)[1]), "r"((a)[2]), "r"((a)[3]), "r"((b)[0]), "r"((b)[1]))

#define CP16(dst, src) asm volatile("cp.async.cg.shared.global [%0], [%1], 16;" :: "r"(dst), "l"(src))
#define CP_COMMIT()    asm volatile("cp.async.commit_group;")
#define CP_WAIT1()     asm volatile("cp.async.wait_group 1;" ::: "memory")
#define CP_WAIT0()     asm volatile("cp.async.wait_group 0;" ::: "memory")

__device__ __forceinline__ void split2h(float x, float y, uint32_t& hp, uint32_t& lp) {
    __half2 h = __floats2half2_rn(x, y);
    float lx = x - __half2float(__low2half(h));
    float ly = y - __half2float(__high2half(h));
    __half2 l = __floats2half2_rn(lx, ly);
    hp = *(uint32_t*)&h; lp = *(uint32_t*)&l;
}
__device__ __forceinline__ uint32_t pack_f16(float x, float y) {
    __half2 h = __floats2half2_rn(x, y);
    return *(uint32_t*)&h;
}

__device__ __forceinline__ int nsp_of(int qb) { return (2 * qb + 9) >> 3; }

// ---------------- merged weight prep: all -> [N][K] fp16 ----------------
__global__ void wprep4(const float* __restrict__ s0, f16* __restrict__ h0,
                       const float* __restrict__ s1, f16* __restrict__ h1,
                       const float* __restrict__ s2, f16* __restrict__ h2,
                       const float* __restrict__ s3, f16* __restrict__ h3) {
    __shared__ float t[32][33];
    int b = blockIdx.x;
    const float* src; f16* dh; int K, N, nx, rb;
    if (b < 768)       { src = s0; dh = h0; K = 512;  N = 1536; nx = 48; rb = b; }
    else if (b < 1024) { src = s1; dh = h1; K = 512;  N = 512;  nx = 16; rb = b - 768; }
    else if (b < 1536) { src = s2; dh = h2; K = 512;  N = 1024; nx = 32; rb = b - 1024; }
    else               { src = s3; dh = h3; K = 1024; N = 512;  nx = 16; rb = b - 1536; }
    int n0 = (rb % nx) * 32, k0 = (rb / nx) * 32;
    int tx = threadIdx.x & 31, ty = threadIdx.x >> 5;
    #pragma unroll
    for (int i = 0; i < 32; i += 8)
        t[ty + i][tx] = src[(size_t)(k0 + ty + i) * N + n0 + tx];
    __syncthreads();
    #pragma unroll
    for (int i = 0; i < 32; i += 8)
        dh[(size_t)(n0 + ty + i) * K + k0 + tx] = __float2half(t[tx][ty + i]);
}

// ---------------- LayerNorm -> fp16 split ----------------
__global__ void ln_split(const float* __restrict__ x, const float* __restrict__ g,
                         const float* __restrict__ b, f16* __restrict__ oh,
                         f16* __restrict__ ol) {
    __shared__ float red[32];
    __shared__ float s_mean, s_rstd;
    int row = blockIdx.x;
    int tid = threadIdx.x;
    float2 v = *(const float2*)(x + (size_t)row * D_DIM + tid * 2);

    float sum = v.x + v.y;
    #pragma unroll
    for (int o = 16; o > 0; o >>= 1) sum += __shfl_down_sync(0xffffffffu, sum, o);
    if ((tid & 31) == 0) red[tid >> 5] = sum;
    __syncthreads();
    if (tid < 32) {
        float t = (tid < 8) ? red[tid] : 0.f;
        #pragma unroll
        for (int o = 4; o > 0; o >>= 1) t += __shfl_down_sync(0xffffffffu, t, o);
        if (tid == 0) s_mean = t * (1.f / D_DIM);
    }
    __syncthreads();
    float mean = s_mean;
    float d0 = v.x - mean, d1 = v.y - mean;

    float vs = d0 * d0 + d1 * d1;
    #pragma unroll
    for (int o = 16; o > 0; o >>= 1) vs += __shfl_down_sync(0xffffffffu, vs, o);
    if ((tid & 31) == 0) red[tid >> 5] = vs;
    __syncthreads();
    if (tid < 32) {
        float t = (tid < 8) ? red[tid] : 0.f;
        #pragma unroll
        for (int o = 4; o > 0; o >>= 1) t += __shfl_down_sync(0xffffffffu, t, o);
        if (tid == 0) s_rstd = rsqrtf(t * (1.f / D_DIM) + EPS_LN);
    }
    __syncthreads();
    float rstd = s_rstd;

    int c = tid * 2;
    float2 gg = *(const float2*)(g + c);
    float2 bb = *(const float2*)(b + c);
    float ox = d0 * rstd * gg.x + bb.x;
    float oy = d1 * rstd * gg.y + bb.y;
    uint32_t hp, lp;
    split2h(ox, oy, hp, lp);
    *(uint32_t*)(oh + (size_t)row * D_DIM + c) = hp;
    *(uint32_t*)(ol + (size_t)row * D_DIM + c) = lp;
}

// ---------------- fp16 2-pass GEMM (A split hi/lo, B single) ----------------
// EPI: 0 = bias -> qkv routing (Q split / K hi / V transposed)
//      1 = bias+GELU -> fp16 split; 2 = bias+residual -> fp32
template <int BN, int K_TOT, int EPI, int STAGES>
__global__ void __launch_bounds__(256, 2)
gemm2(const f16* __restrict__ Ah, const f16* __restrict__ Al,
      const f16* __restrict__ B,
      const float* __restrict__ bias, const float* __restrict__ res,
      float* __restrict__ Cf, f16* __restrict__ Ch, f16* __restrict__ Cl,
      f16* __restrict__ Vt, int N) {
    constexpr int WARPS_N = BN / 32;
    constexpr int WARPS_M = 8 / WARPS_N;
    constexpr int WM = 128 / WARPS_M;
    constexpr int MI = WM / 16;
    constexpr int A_SZ = 128 * 80;
    constexpr int B_SZ = BN * 80;
    constexpr int B_OFF = 2 * A_SZ;
    constexpr int BUF = 2 * A_SZ + B_SZ;
    constexpr int NS = K_TOT / 32;

    extern __shared__ __align__(16) char smx[];
    const uint32_t sbase = smem_u32(smx);

    int tid = threadIdx.x;
    int wid = tid >> 5;
    int l = tid & 31;
    int bm = blockIdx.y * 128, bn = blockIdx.x * BN;
    int warp_m = wid / WARPS_N, warp_n = wid % WARPS_N;

    float d[MI][4][4];
    #pragma unroll
    for (int i = 0; i < MI; i++)
        #pragma unroll
        for (int j = 0; j < 4; j++)
            #pragma unroll
            for (int k = 0; k < 4; k++) d[i][j][k] = 0.f;

    int lb = l & 15;
    uint32_t a_rel = (uint32_t)(warp_m * WM + lb) * 80 + (uint32_t)(l >> 4) * 16;
    uint32_t b_rel = B_OFF + (uint32_t)(warp_n * 32 + (l >> 4) * 8 + (l & 7)) * 80 +
                     (uint32_t)((l >> 3) & 1) * 16;

    int a_cc = tid & 3, a_row = tid >> 2;
    constexpr int BCH = BN * 4;

    auto issue = [&](int s) {
        int k0 = s * 32;
        uint32_t bufb = sbase + (uint32_t)((s % STAGES) * BUF);
        #pragma unroll
        for (int t = 0; t < 2; t++) {
            int row = a_row + t * 64;
            size_t so = (size_t)(bm + row) * K_TOT + k0 + a_cc * 8;
            uint32_t dst = bufb + (uint32_t)(row * 80 + a_cc * 16);
            CP16(dst, Ah + so);
            CP16(dst + A_SZ, Al + so);
        }
        #pragma unroll
        for (int t = 0; t < BCH / 256; t++) {
            int c = tid + t * 256;
            int cc = c & 3, row = c >> 2;
            size_t so = (size_t)(bn + row) * K_TOT + k0 + cc * 8;
            CP16(bufb + B_OFF + (uint32_t)(row * 80 + cc * 16), B + so);
        }
    };

    auto compute = [&](int s) {
        uint32_t cb = sbase + (uint32_t)((s % STAGES) * BUF);
        #pragma unroll
        for (int ks = 0; ks < 2; ks++) {
            uint32_t bh[4][2];
            #pragma unroll
            for (int pj = 0; pj < 2; pj++) {
                uint32_t ba = cb + b_rel + pj * 16 * 80 + ks * 32;
                LDMATRIX_X4(bh[2 * pj][0], bh[2 * pj][1], bh[2 * pj + 1][0], bh[2 * pj + 1][1], ba);
            }
            #pragma unroll
            for (int mi = 0; mi < MI; mi++) {
                uint32_t ah[4], al[4];
                uint32_t aa = cb + a_rel + mi * 16 * 80 + ks * 32;
                LDMATRIX_X4(ah[0], ah[1], ah[2], ah[3], aa);
                LDMATRIX_X4(al[0], al[1], al[2], al[3], aa + A_SZ);
                #pragma unroll
                for (int nj = 0; nj < 4; nj++) {
                    MMA_F16(d[mi][nj], ah, bh[nj]);
                    MMA_F16(d[mi][nj], al, bh[nj]);
                }
            }
        }
    };

    if (STAGES == 3) {
        issue(0); CP_COMMIT();
        issue(1); CP_COMMIT();
        for (int s = 0; s < NS; s++) {
            if (s == NS - 1) CP_WAIT0(); else CP_WAIT1();
            __syncthreads();
            compute(s);
            if (s + 2 < NS) { issue(s + 2); CP_COMMIT(); }
        }
    } else {
        issue(0); CP_COMMIT();
        for (int s = 0; s < NS; s++) {
            if (s + 1 < NS) { issue(s + 1); CP_COMMIT(); CP_WAIT1(); }
            else CP_WAIT0();
            __syncthreads();
            compute(s);
            __syncthreads();
        }
    }

    #pragma unroll
    for (int mi = 0; mi < MI; mi++) {
        int row0 = bm + warp_m * WM + mi * 16 + (l >> 2);
        #pragma unroll
        for (int nj = 0; nj < 4; nj++) {
            int col = bn + warp_n * 32 + nj * 8 + (l & 3) * 2;
            float2 bb = *(const float2*)(bias + col);
            #pragma unroll
            for (int half = 0; half < 2; half++) {
                int row = row0 + half * 8;
                float vx = d[mi][nj][half * 2 + 0] + bb.x;
                float vy = d[mi][nj][half * 2 + 1] + bb.y;
                if (EPI == 0) {
                    if (col < 512) {
                        uint32_t hp, lp;
                        split2h(vx, vy, hp, lp);
                        *(uint32_t*)(Ch + (size_t)row * 1024 + col) = hp;
                        *(uint32_t*)(Cl + (size_t)row * 1024 + col) = lp;
                    } else if (col < 1024) {
                        *(uint32_t*)(Ch + (size_t)row * 1024 + col) = pack_f16(vx, vy);
                    } else {
                        int hc = col - 1024;
                        size_t i0 = (size_t)hc * S_LEN + row;
                        Vt[i0] = __float2half(vx);
                        Vt[i0 + S_LEN] = __float2half(vy);
                    }
                } else if (EPI == 1) {
                    vx = 0.5f * vx * (1.f + erff(vx * 0.70710678118654752f));
                    vy = 0.5f * vy * (1.f + erff(vy * 0.70710678118654752f));
                    uint32_t hp, lp;
                    split2h(vx, vy, hp, lp);
                    *(uint32_t*)(Ch + (size_t)row * N + col) = hp;
                    *(uint32_t*)(Cl + (size_t)row * N + col) = lp;
                } else {
                    float2 rr = *(const float2*)(res + (size_t)row * N + col);
                    float2 o2; o2.x = vx + rr.x; o2.y = vy + rr.y;
                    *(float2*)(Cf + (size_t)row * N + col) = o2;
                }
            }
        }
    }
}

// ---------------- flash attention: QK fp16 2-pass, PV fp16 1-pass, split-K ----------------
#define AST 144
#define QSZ (128 * AST)
#define KSZ (64 * AST)
#define KVBUF (2 * KSZ)
#define KV0 (2 * QSZ)
#define ATT_SMEM (KV0 + 2 * KVBUF)

__global__ void __launch_bounds__(256, 2)
attn_cp(const f16* __restrict__ QKh, const f16* __restrict__ QKl,
        const f16* __restrict__ Vt,
        f16* __restrict__ AOh, f16* __restrict__ AOl,
        float* __restrict__ Po, float* __restrict__ Pml) {
    extern __shared__ char sm[];
    const uint32_t sbase = smem_u32(sm);

    int gx = (int)gridDim.x - 1 - (int)blockIdx.x;
    int qb = 0, acc = 0;
    while (acc + nsp_of(qb) <= gx) { acc += nsp_of(qb); qb++; }
    int sp = gx - acc;
    int nsp = nsp_of(qb);
    int total = 2 * qb + 2;
    int chunk = (total + nsp - 1) / nsp;
    int kb_begin = sp * chunk;
    int kb_end = min(total, kb_begin + chunk);
    int pidx = gx * 8 + (int)blockIdx.y;

    int h = blockIdx.y;
    int tid = threadIdx.x;
    int w = tid >> 5;
    int l = tid & 31;
    int lb = l & 15;

    int q_cc = tid & 7, q_row = tid >> 3;
    auto issueQ = [&]() {
        #pragma unroll
        for (int t = 0; t < 4; t++) {
            int row = q_row + t * 32;
            size_t so = (size_t)(qb * 128 + row) * 1024 + h * 64 + q_cc * 8;
            uint32_t dst = sbase + (uint32_t)(row * AST + q_cc * 16);
            CP16(dst, QKh + so);
            CP16(dst + QSZ, QKl + so);
        }
    };
    auto issueKV = [&](int kb) {
        uint32_t base = sbase + KV0 + (uint32_t)((kb & 1) * KVBUF);
        #pragma unroll
        for (int t = 0; t < 2; t++) {
            int row = q_row + t * 32;
            uint32_t doff = (uint32_t)(row * AST + q_cc * 16);
            size_t sk = (size_t)(kb * 64 + row) * 1024 + 512 + h * 64 + q_cc * 8;
            CP16(base + doff, QKh + sk);
            size_t sv = (size_t)(h * 64 + row) * S_LEN + kb * 64 + q_cc * 8;
            CP16(base + KSZ + doff, Vt + sv);
        }
    };

    issueQ();
    issueKV(kb_begin); CP_COMMIT();

    float o[8][4];
    #pragma unroll
    for (int j = 0; j < 8; j++)
        #pragma unroll
        for (int k = 0; k < 4; k++) o[j][k] = 0.f;
    float m0 = -1e30f, m1 = -1e30f, l0 = 0.f, l1 = 0.f;

    uint32_t aq = sbase + (uint32_t)((16 * w + lb) * AST) + (uint32_t)(l >> 4) * 16;
    uint32_t kv_rel = (uint32_t)(((l >> 4) * 8 + (l & 7)) * AST) + (uint32_t)((l >> 3) & 1) * 16;

    int row0g = qb * 128 + 16 * w + (l >> 2);

    for (int kb = kb_begin; kb < kb_end; kb++) {
        if (kb + 1 < kb_end) { issueKV(kb + 1); CP_COMMIT(); CP_WAIT1(); }
        else CP_WAIT0();
        __syncthreads();

        uint32_t kvb = sbase + KV0 + (uint32_t)((kb & 1) * KVBUF);
        uint32_t bk = kvb + kv_rel;
        uint32_t bv = kvb + KSZ + kv_rel;

        // ---- S = Q K^T (fp16 2-pass: Qh*K + Ql*K) ----
        float s[8][4];
        #pragma unroll
        for (int j = 0; j < 8; j++)
            #pragma unroll
            for (int k = 0; k < 4; k++) s[j][k] = 0.f;
        #pragma unroll
        for (int ks = 0; ks < 4; ks++) {
            uint32_t ah[4], al[4];
            LDMATRIX_X4(ah[0], ah[1], ah[2], ah[3], aq + ks * 32);
            LDMATRIX_X4(al[0], al[1], al[2], al[3], aq + ks * 32 + QSZ);
            #pragma unroll
            for (int jp = 0; jp < 4; jp++) {
                uint32_t bh[2][2];
                uint32_t ba = bk + jp * 16 * AST + ks * 32;
                LDMATRIX_X4(bh[0][0], bh[0][1], bh[1][0], bh[1][1], ba);
                #pragma unroll
                for (int q = 0; q < 2; q++) {
                    int j = 2 * jp + q;
                    MMA_F16(s[j], ah, bh[q]);
                    MMA_F16(s[j], al, bh[q]);
                }
            }
        }

        // ---- scale + causal mask ----
        int cbase = kb * 64 + 2 * (l & 3);
        bool need_mask = (kb >= 2 * qb);
        #pragma unroll
        for (int j = 0; j < 8; j++) {
            #pragma unroll
            for (int k = 0; k < 4; k++) s[j][k] *= 0.125f;
            if (need_mask) {
                int c0 = cbase + 8 * j;
                if (c0 > row0g)     s[j][0] = -1e30f;
                if (c0 + 1 > row0g) s[j][1] = -1e30f;
                if (c0 > row0g + 8)     s[j][2] = -1e30f;
                if (c0 + 1 > row0g + 8) s[j][3] = -1e30f;
            }
        }

        // ---- online softmax ----
        float mn0 = m0, mn1 = m1;
        #pragma unroll
        for (int j = 0; j < 8; j++) {
            mn0 = fmaxf(mn0, fmaxf(s[j][0], s[j][1]));
            mn1 = fmaxf(mn1, fmaxf(s[j][2], s[j][3]));
        }
        mn0 = fmaxf(mn0, __shfl_xor_sync(0xffffffffu, mn0, 1));
        mn0 = fmaxf(mn0, __shfl_xor_sync(0xffffffffu, mn0, 2));
        mn1 = fmaxf(mn1, __shfl_xor_sync(0xffffffffu, mn1, 1));
        mn1 = fmaxf(mn1, __shfl_xor_sync(0xffffffffu, mn1, 2));
        float alpha0 = __expf(m0 - mn0);
        float alpha1 = __expf(m1 - mn1);
        m0 = mn0; m1 = mn1;
        float rs0 = 0.f, rs1 = 0.f;
        #pragma unroll
        for (int j = 0; j < 8; j++) {
            s[j][0] = __expf(s[j][0] - mn0);
            s[j][1] = __expf(s[j][1] - mn0);
            s[j][2] = __expf(s[j][2] - mn1);
            s[j][3] = __expf(s[j][3] - mn1);
            rs0 += s[j][0] + s[j][1];
            rs1 += s[j][2] + s[j][3];
        }
        l0 = l0 * alpha0 + rs0;
        l1 = l1 * alpha1 + rs1;
        #pragma unroll
        for (int j = 0; j < 8; j++) {
            o[j][0] *= alpha0; o[j][1] *= alpha0;
            o[j][2] *= alpha1; o[j][3] *= alpha1;
        }

        // ---- O += P @ V (fp16 single-pass) ----
        #pragma unroll
        for (int ks = 0; ks < 4; ks++) {
            uint32_t pa[4];
            pa[0] = pack_f16(s[2 * ks][0], s[2 * ks][1]);
            pa[1] = pack_f16(s[2 * ks][2], s[2 * ks][3]);
            pa[2] = pack_f16(s[2 * ks + 1][0], s[2 * ks + 1][1]);
            pa[3] = pack_f16(s[2 * ks + 1][2], s[2 * ks + 1][3]);
            #pragma unroll
            for (int jp = 0; jp < 4; jp++) {
                uint32_t vh[2][2];
                uint32_t va = bv + jp * 16 * AST + ks * 32;
                LDMATRIX_X4(vh[0][0], vh[0][1], vh[1][0], vh[1][1], va);
                MMA_F16(o[2 * jp], pa, vh[0]);
                MMA_F16(o[2 * jp + 1], pa, vh[1]);
            }
        }
        __syncthreads();
    }

    // ---- finalize ----
    l0 += __shfl_xor_sync(0xffffffffu, l0, 1);
    l0 += __shfl_xor_sync(0xffffffffu, l0, 2);
    l1 += __shfl_xor_sync(0xffffffffu, l1, 1);
    l1 += __shfl_xor_sync(0xffffffffu, l1, 2);

    if (nsp == 1) {
        float inv0 = 1.f / l0, inv1 = 1.f / l1;
        #pragma unroll
        for (int j = 0; j < 8; j++) {
            int col = h * 64 + 8 * j + 2 * (l & 3);
            uint32_t hp, lp;
            split2h(o[j][0] * inv0, o[j][1] * inv0, hp, lp);
            *(uint32_t*)(AOh + (size_t)row0g * D_DIM + col) = hp;
            *(uint32_t*)(AOl + (size_t)row0g * D_DIM + col) = lp;
            split2h(o[j][2] * inv1, o[j][3] * inv1, hp, lp);
            *(uint32_t*)(AOh + (size_t)(row0g + 8) * D_DIM + col) = hp;
            *(uint32_t*)(AOl + (size_t)(row0g + 8) * D_DIM + col) = lp;
        }
    } else {
        float* po = Po + (size_t)pidx * 8192;
        float* pml = Pml + (size_t)pidx * 256;
        int r0 = 16 * w + (l >> 2);
        #pragma unroll
        for (int j = 0; j < 8; j++) {
            int c = 8 * j + 2 * (l & 3);
            float2 v0; v0.x = o[j][0]; v0.y = o[j][1];
            float2 v1; v1.x = o[j][2]; v1.y = o[j][3];
            *(float2*)(po + r0 * 64 + c) = v0;
            *(float2*)(po + (r0 + 8) * 64 + c) = v1;
        }
        if ((l & 3) == 0) {
            pml[r0 * 2] = m0; pml[r0 * 2 + 1] = l0;
            pml[(r0 + 8) * 2] = m1; pml[(r0 + 8) * 2 + 1] = l1;
        }
    }
}

// ---------------- split-K combine (qb >= 4) ----------------
__global__ void attn_combine(const float* __restrict__ Po, const float* __restrict__ Pml,
                             f16* __restrict__ AOh, f16* __restrict__ AOl) {
    int qb = 4 + (int)blockIdx.x;
    int h = blockIdx.y;
    int nsp = nsp_of(qb);
    int base = 0;
    for (int i = 0; i < qb; i++) base += nsp_of(i);
    int tid = threadIdx.x;
    int row = tid >> 1;
    int c0 = (tid & 1) * 32;

    float mi[8], li[8], wgt[8];
    float mg = -1e30f;
    for (int i = 0; i < nsp; i++) {
        const float* pml = Pml + (size_t)((base + i) * 8 + h) * 256;
        mi[i] = pml[row * 2];
        li[i] = pml[row * 2 + 1];
        mg = fmaxf(mg, mi[i]);
    }
    float L = 0.f;
    for (int i = 0; i < nsp; i++) { wgt[i] = __expf(mi[i] - mg); L += li[i] * wgt[i]; }
    float invL = 1.f / L;

    size_t orow = (size_t)(qb * 128 + row) * D_DIM + h * 64;
    for (int c = c0; c < c0 + 32; c += 2) {
        float x = 0.f, y = 0.f;
        for (int i = 0; i < nsp; i++) {
            const float* p = Po + (size_t)((base + i) * 8 + h) * 8192 + row * 64 + c;
            x += p[0] * wgt[i];
            y += p[1] * wgt[i];
        }
        x *= invL; y *= invL;
        uint32_t hp, lp;
        split2h(x, y, hp, lp);
        *(uint32_t*)(AOh + orow + c) = hp;
        *(uint32_t*)(AOl + orow + c) = lp;
    }
}

// ---------------- launch ----------------
extern "C" void kernel_launch(void* const* d_in, const int* in_sizes, int n_in,
                              void* d_out, int out_size) {
    const float* x    = (const float*)d_in[0];
    const float* wqkv = (const float*)d_in[1];
    const float* bqkv = (const float*)d_in[2];
    const float* wout = (const float*)d_in[3];
    const float* bout = (const float*)d_in[4];
    const float* wff1 = (const float*)d_in[5];
    const float* bff1 = (const float*)d_in[6];
    const float* wff2 = (const float*)d_in[7];
    const float* bff2 = (const float*)d_in[8];
    const float* g1   = (const float*)d_in[9];
    const float* bt1  = (const float*)d_in[10];
    const float* g2   = (const float*)d_in[11];
    const float* bt2  = (const float*)d_in[12];
    float* out = (float*)d_out;

    f16 *hh, *hl, *wqT, *woT, *w1T, *w2T, *qkh, *qkl, *vt;
    f16 *aoh, *aol, *h2h, *h2l, *ffh, *ffl;
    float *x1, *po, *pml;
    cudaGetSymbolAddress((void**)&hh,  g_h_hi);   cudaGetSymbolAddress((void**)&hl,  g_h_lo);
    cudaGetSymbolAddress((void**)&wqT, g_wqkvT);
    cudaGetSymbolAddress((void**)&woT, g_woutT);
    cudaGetSymbolAddress((void**)&w1T, g_wff1T);
    cudaGetSymbolAddress((void**)&w2T, g_wff2T);
    cudaGetSymbolAddress((void**)&qkh, g_qk_hi);  cudaGetSymbolAddress((void**)&qkl, g_qk_lo);
    cudaGetSymbolAddress((void**)&vt,  g_vt);
    cudaGetSymbolAddress((void**)&aoh, g_ao_hi);  cudaGetSymbolAddress((void**)&aol, g_ao_lo);
    cudaGetSymbolAddress((void**)&h2h, g_h2_hi);  cudaGetSymbolAddress((void**)&h2l, g_h2_lo);
    cudaGetSymbolAddress((void**)&ffh, g_ff_hi);  cudaGetSymbolAddress((void**)&ffl, g_ff_lo);
    cudaGetSymbolAddress((void**)&x1,  g_x1);
    cudaGetSymbolAddress((void**)&po,  g_po);
    cudaGetSymbolAddress((void**)&pml, g_pml);

    const int GS2_128 = 2 * (2 * 128 * 80 + 128 * 80);   // 61440 (qkv/ff1, 2-stage)
    const int GS2_64  = 3 * (2 * 128 * 80 + 64 * 80);    // 76800 (out/ff2, 3-stage)
    cudaFuncSetAttribute(gemm2<128, 512, 0, 2>, cudaFuncAttributeMaxDynamicSharedMemorySize, GS2_128);
    cudaFuncSetAttribute(gemm2<128, 512, 1, 2>, cudaFuncAttributeMaxDynamicSharedMemorySize, GS2_128);
    cudaFuncSetAttribute(gemm2<64, 512, 2, 3>,  cudaFuncAttributeMaxDynamicSharedMemorySize, GS2_64);
    cudaFuncSetAttribute(gemm2<64, 1024, 2, 3>, cudaFuncAttributeMaxDynamicSharedMemorySize, GS2_64);
    cudaFuncSetAttribute(attn_cp, cudaFuncAttributeMaxDynamicSharedMemorySize, ATT_SMEM);

    // 0) weight prep (all fp16)
    wprep4<<<2048, 256>>>(wqkv, wqT, wout, woT, wff1, w1T, wff2, w2T);
    // 1) h = LN1(x) -> fp16 split
    ln_split<<<S_LEN, 256>>>(x, g1, bt1, hh, hl);
    // 2) qkv (fp16 2-pass) -> Q split / K hi / V transposed
    gemm2<128, 512, 0, 2><<<dim3(12, 32), 256, GS2_128>>>(hh, hl, wqT, bqkv, nullptr,
        nullptr, qkh, qkl, vt, 1536);
    // 3) attention (QK fp16 2-pass, PV fp16 1-pass) -> ao fp16 split
    attn_cp<<<dim3(144, 8), 256, ATT_SMEM>>>(qkh, qkl, vt, aoh, aol, po, pml);
    attn_combine<<<dim3(28, 8), 256>>>(po, pml, aoh, aol);
    // 4) x1 = x + ao @ w_out + b_out
    gemm2<64, 512, 2, 3><<<dim3(8, 32), 256, GS2_64>>>(aoh, aol, woT, bout, x, x1,
        nullptr, nullptr, nullptr, 512);
    // 5) h2 = LN2(x1) -> fp16 split
    ln_split<<<S_LEN, 256>>>(x1, g2, bt2, h2h, h2l);
    // 6) ff = gelu(h2 @ w_ff1 + b_ff1) -> fp16 split
    gemm2<128, 512, 1, 2><<<dim3(8, 32), 256, GS2_128>>>(h2h, h2l, w1T, bff1, nullptr,
        nullptr, ffh, ffl, nullptr, 1024);
    // 7) out = x1 + ff @ w_ff2 + b_ff2
    gemm2<64, 1024, 2, 3><<<dim3(8, 32), 256, GS2_64>>>(ffh, ffl, w2T, bff2, x1, out,
        nullptr, nullptr, nullptr, 512);
}

// round 14
// speedup vs baseline: 1.7493x; 1.3146x over previous
#include <cuda_runtime.h>
#include <cuda_fp16.h>
#include <math.h>
#include <stdint.h>

typedef __half f16;

#define S_LEN 4096
#define D_DIM 512
#define FF_DIM 1024
#define EPS_LN 1e-5f

// ---------------- persistent scratch (no allocations) ----------------
__device__ f16  g_h [S_LEN * D_DIM];
__device__ f16  g_wqkvT[1536 * 512];
__device__ f16  g_woutT[512 * 512];
__device__ f16  g_wff1T[1024 * 512];
__device__ f16  g_wff2T[512 * 1024];
__device__ f16  g_qk[S_LEN * 1024];                  // q cols 0..511, k cols 512..1023
__device__ f16  g_vt[512 * S_LEN];                   // [h*64+dh][seq]
__device__ f16  g_ao[S_LEN * D_DIM];
__device__ f16  g_h2[S_LEN * D_DIM];
__device__ f16  g_ff[S_LEN * FF_DIM];
__device__ float g_x1[S_LEN * D_DIM];
__device__ float g_po[1152 * 128 * 64];
__device__ float g_pml[1152 * 256];

__device__ __forceinline__ uint32_t smem_u32(const void* p) {
    uint32_t a;
    asm("{ .reg .u64 t; cvta.to.shared.u64 t, %1; cvt.u32.u64 %0, t; }" : "=r"(a) : "l"(p));
    return a;
}

#define LDMATRIX_X4(r0, r1, r2, r3, a) \
    asm volatile("ldmatrix.sync.aligned.m8n8.x4.shared.b16 {%0,%1,%2,%3}, [%4];" \
        : "=r"(r0), "=r"(r1), "=r"(r2), "=r"(r3) : "r"(a))
#define MMA_F16(d, a, b) \
    asm volatile("mma.sync.aligned.m16n8k16.row.col.f32.f16.f16.f32 " \
        "{%0,%1,%2,%3}, {%4,%5,%6,%7}, {%8,%9}, {%0,%1,%2,%3};" \
        : "+f"((d)[0]), "+f"((d)[1]), "+f"((d)[2]), "+f"((d)[3]) \
        : "r"((a)[0]), "r"((a)[1]), "r"((a)[2]), "r"((a)[3]), "r"((b)[0]), "r"((b)[1]))

#define CP16(dst, src) asm volatile("cp.async.cg.shared.global [%0], [%1], 16;" :: "r"(dst), "l"(src))
#define CP_COMMIT()    asm volatile("cp.async.commit_group;")
#define CP_WAIT1()     asm volatile("cp.async.wait_group 1;" ::: "memory")
#define CP_WAIT0()     asm volatile("cp.async.wait_group 0;" ::: "memory")

__device__ __forceinline__ uint32_t pack_f16(float x, float y) {
    __half2 h = __floats2half2_rn(x, y);
    return *(uint32_t*)&h;
}

__device__ __forceinline__ int nsp_of(int qb) { return (2 * qb + 9) >> 3; }

// ---------------- merged weight prep: all -> [N][K] fp16 ----------------
__global__ void wprep4(const float* __restrict__ s0, f16* __restrict__ h0,
                       const float* __restrict__ s1, f16* __restrict__ h1,
                       const float* __restrict__ s2, f16* __restrict__ h2,
                       const float* __restrict__ s3, f16* __restrict__ h3) {
    __shared__ float t[32][33];
    int b = blockIdx.x;
    const float* src; f16* dh; int K, N, nx, rb;
    if (b < 768)       { src = s0; dh = h0; K = 512;  N = 1536; nx = 48; rb = b; }
    else if (b < 1024) { src = s1; dh = h1; K = 512;  N = 512;  nx = 16; rb = b - 768; }
    else if (b < 1536) { src = s2; dh = h2; K = 512;  N = 1024; nx = 32; rb = b - 1024; }
    else               { src = s3; dh = h3; K = 1024; N = 512;  nx = 16; rb = b - 1536; }
    int n0 = (rb % nx) * 32, k0 = (rb / nx) * 32;
    int tx = threadIdx.x & 31, ty = threadIdx.x >> 5;
    #pragma unroll
    for (int i = 0; i < 32; i += 8)
        t[ty + i][tx] = src[(size_t)(k0 + ty + i) * N + n0 + tx];
    __syncthreads();
    #pragma unroll
    for (int i = 0; i < 32; i += 8)
        dh[(size_t)(n0 + ty + i) * K + k0 + tx] = __float2half(t[tx][ty + i]);
}

// ---------------- LayerNorm -> fp16 ----------------
__global__ void ln_f16(const float* __restrict__ x, const float* __restrict__ g,
                       const float* __restrict__ b, f16* __restrict__ oh) {
    __shared__ float red[32];
    __shared__ float s_mean, s_rstd;
    int row = blockIdx.x;
    int tid = threadIdx.x;
    float2 v = *(const float2*)(x + (size_t)row * D_DIM + tid * 2);

    float sum = v.x + v.y;
    #pragma unroll
    for (int o = 16; o > 0; o >>= 1) sum += __shfl_down_sync(0xffffffffu, sum, o);
    if ((tid & 31) == 0) red[tid >> 5] = sum;
    __syncthreads();
    if (tid < 32) {
        float t = (tid < 8) ? red[tid] : 0.f;
        #pragma unroll
        for (int o = 4; o > 0; o >>= 1) t += __shfl_down_sync(0xffffffffu, t, o);
        if (tid == 0) s_mean = t * (1.f / D_DIM);
    }
    __syncthreads();
    float mean = s_mean;
    float d0 = v.x - mean, d1 = v.y - mean;

    float vs = d0 * d0 + d1 * d1;
    #pragma unroll
    for (int o = 16; o > 0; o >>= 1) vs += __shfl_down_sync(0xffffffffu, vs, o);
    if ((tid & 31) == 0) red[tid >> 5] = vs;
    __syncthreads();
    if (tid < 32) {
        float t = (tid < 8) ? red[tid] : 0.f;
        #pragma unroll
        for (int o = 4; o > 0; o >>= 1) t += __shfl_down_sync(0xffffffffu, t, o);
        if (tid == 0) s_rstd = rsqrtf(t * (1.f / D_DIM) + EPS_LN);
    }
    __syncthreads();
    float rstd = s_rstd;

    int c = tid * 2;
    float2 gg = *(const float2*)(g + c);
    float2 bb = *(const float2*)(b + c);
    float ox = d0 * rstd * gg.x + bb.x;
    float oy = d1 * rstd * gg.y + bb.y;
    *(uint32_t*)(oh + (size_t)row * D_DIM + c) = pack_f16(ox, oy);
}

// ---------------- single-pass fp16 GEMM, 3-stage cp.async ----------------
// EPI: 0 = bias -> qkv routing; 1 = bias+GELU -> fp16; 2 = bias+residual -> fp32
template <int BN, int K_TOT, int EPI>
__global__ void __launch_bounds__(256, 2)
gemm1(const f16* __restrict__ A, const f16* __restrict__ B,
      const float* __restrict__ bias, const float* __restrict__ res,
      float* __restrict__ Cf, f16* __restrict__ C16, f16* __restrict__ Vt, int N) {
    constexpr int WARPS_N = BN / 32;
    constexpr int WARPS_M = 8 / WARPS_N;
    constexpr int WM = 128 / WARPS_M;
    constexpr int MI = WM / 16;
    constexpr int A_SZ = 128 * 80;
    constexpr int B_SZ = BN * 80;
    constexpr int BUF = A_SZ + B_SZ;
    constexpr int NS = K_TOT / 32;
    constexpr int STAGES = 3;

    extern __shared__ __align__(16) char smx[];
    const uint32_t sbase = smem_u32(smx);

    int tid = threadIdx.x;
    int wid = tid >> 5;
    int l = tid & 31;
    int bm = blockIdx.y * 128, bn = blockIdx.x * BN;
    int warp_m = wid / WARPS_N, warp_n = wid % WARPS_N;

    float d[MI][4][4];
    #pragma unroll
    for (int i = 0; i < MI; i++)
        #pragma unroll
        for (int j = 0; j < 4; j++)
            #pragma unroll
            for (int k = 0; k < 4; k++) d[i][j][k] = 0.f;

    int lb = l & 15;
    uint32_t a_rel = (uint32_t)(warp_m * WM + lb) * 80 + (uint32_t)(l >> 4) * 16;
    uint32_t b_rel = A_SZ + (uint32_t)(warp_n * 32 + (l >> 4) * 8 + (l & 7)) * 80 +
                     (uint32_t)((l >> 3) & 1) * 16;

    int a_cc = tid & 1, a_row = tid >> 1;       // 2 chunks per A row
    constexpr int BCH = BN * 2;

    auto issue = [&](int s) {
        int k0 = s * 32;
        uint32_t bufb = sbase + (uint32_t)((s % STAGES) * BUF);
        {
            size_t so = (size_t)(bm + a_row) * K_TOT + k0 + a_cc * 8 + (a_cc ? 8 : 0);
            // chunk cc covers elements cc*16..cc*16+7? No: 2 chunks of 16B = 8 f16 each? 32 f16 per row needs 4 chunks.
        }
    };
    // (replaced below — see issue2)
    (void)issue;

    // A row = 32 f16 = 64 bytes = 4 chunks; 128 rows * 4 = 512 chunks -> 2 per thread
    int ac = tid & 3, ar = tid >> 2;            // rows 0..63 (+64)
    auto issue2 = [&](int s) {
        int k0 = s * 32;
        uint32_t bufb = sbase + (uint32_t)((s % STAGES) * BUF);
        #pragma unroll
        for (int t = 0; t < 2; t++) {
            int row = ar + t * 64;
            size_t so = (size_t)(bm + row) * K_TOT + k0 + ac * 8;
            CP16(bufb + (uint32_t)(row * 80 + ac * 16), A + so);
        }
        #pragma unroll
        for (int t = 0; t < BCH / 256 + (BCH % 256 ? 1 : 0); t++) {
            int c = tid + t * 256;
            if (BCH % 256 && c >= BCH) break;
            int cc = c & 1, row = c >> 1;
            size_t so = (size_t)(bn + row) * K_TOT + k0 + cc * 8 + (cc ? 8 : 0) - (cc ? 8 : 0);
            // B row = 32 f16 = 4 chunks too! fix below
            (void)so; (void)cc; (void)row;
        }
    };
    (void)issue2;

    // Correct loader: both A and B rows are 32 f16 = 64B = 4 x 16B chunks.
    // A: 512 chunks (2/thread). B: BN*4 chunks (2/thread for BN=128, 1/thread for BN=64).
    auto issue3 = [&](int s) {
        int k0 = s * 32;
        uint32_t bufb = sbase + (uint32_t)((s % STAGES) * BUF);
        #pragma unroll
        for (int t = 0; t < 2; t++) {
            int row = ar + t * 64;
            size_t so = (size_t)(bm + row) * K_TOT + k0 + ac * 8;
            CP16(bufb + (uint32_t)(row * 80 + ac * 16), A + so);
        }
        #pragma unroll
        for (int t = 0; t < (BN * 4) / 256; t++) {
            int c = tid + t * 256;
            int cc = c & 3, row = c >> 2;
            size_t so = (size_t)(bn + row) * K_TOT + k0 + cc * 8;
            CP16(bufb + A_SZ + (uint32_t)(row * 80 + cc * 16), B + so);
        }
        if ((BN * 4) % 256) {   // BN=64: 256 chunks exactly, no remainder; keep for safety
        }
    };

    auto compute = [&](int s) {
        uint32_t cb = sbase + (uint32_t)((s % STAGES) * BUF);
        #pragma unroll
        for (int ks = 0; ks < 2; ks++) {
            uint32_t bh[4][2];
            #pragma unroll
            for (int pj = 0; pj < 2; pj++) {
                uint32_t ba = cb + b_rel + pj * 16 * 80 + ks * 32;
                LDMATRIX_X4(bh[2 * pj][0], bh[2 * pj][1], bh[2 * pj + 1][0], bh[2 * pj + 1][1], ba);
            }
            #pragma unroll
            for (int mi = 0; mi < MI; mi++) {
                uint32_t ah[4];
                uint32_t aa = cb + a_rel + mi * 16 * 80 + ks * 32;
                LDMATRIX_X4(ah[0], ah[1], ah[2], ah[3], aa);
                #pragma unroll
                for (int nj = 0; nj < 4; nj++)
                    MMA_F16(d[mi][nj], ah, bh[nj]);
            }
        }
    };

    issue3(0); CP_COMMIT();
    issue3(1); CP_COMMIT();
    for (int s = 0; s < NS; s++) {
        if (s == NS - 1) CP_WAIT0(); else CP_WAIT1();
        __syncthreads();
        compute(s);
        if (s + 2 < NS) { issue3(s + 2); CP_COMMIT(); }
    }

    #pragma unroll
    for (int mi = 0; mi < MI; mi++) {
        int row0 = bm + warp_m * WM + mi * 16 + (l >> 2);
        #pragma unroll
        for (int nj = 0; nj < 4; nj++) {
            int col = bn + warp_n * 32 + nj * 8 + (l & 3) * 2;
            float2 bb = *(const float2*)(bias + col);
            #pragma unroll
            for (int half = 0; half < 2; half++) {
                int row = row0 + half * 8;
                float vx = d[mi][nj][half * 2 + 0] + bb.x;
                float vy = d[mi][nj][half * 2 + 1] + bb.y;
                if (EPI == 0) {
                    if (col < 1024) {
                        *(uint32_t*)(C16 + (size_t)row * 1024 + col) = pack_f16(vx, vy);
                    } else {
                        int hc = col - 1024;
                        size_t i0 = (size_t)hc * S_LEN + row;
                        Vt[i0] = __float2half(vx);
                        Vt[i0 + S_LEN] = __float2half(vy);
                    }
                } else if (EPI == 1) {
                    vx = 0.5f * vx * (1.f + erff(vx * 0.70710678118654752f));
                    vy = 0.5f * vy * (1.f + erff(vy * 0.70710678118654752f));
                    *(uint32_t*)(C16 + (size_t)row * N + col) = pack_f16(vx, vy);
                } else {
                    float2 rr = *(const float2*)(res + (size_t)row * N + col);
                    float2 o2; o2.x = vx + rr.x; o2.y = vy + rr.y;
                    *(float2*)(Cf + (size_t)row * N + col) = o2;
                }
            }
        }
    }
}

// ---------------- flash attention: all fp16 single-pass, split-K ----------------
#define AST 144
#define QSZ (128 * AST)
#define KSZ (64 * AST)
#define KVBUF (2 * KSZ)
#define ATT_SMEM (QSZ + 2 * KVBUF)   // 55296

__global__ void __launch_bounds__(256, 2)
attn_cp(const f16* __restrict__ QK, const f16* __restrict__ Vt,
        f16* __restrict__ AO, float* __restrict__ Po, float* __restrict__ Pml) {
    extern __shared__ char sm[];
    const uint32_t sbase = smem_u32(sm);

    int gx = (int)gridDim.x - 1 - (int)blockIdx.x;
    int qb = 0, acc = 0;
    while (acc + nsp_of(qb) <= gx) { acc += nsp_of(qb); qb++; }
    int sp = gx - acc;
    int nsp = nsp_of(qb);
    int total = 2 * qb + 2;
    int chunk = (total + nsp - 1) / nsp;
    int kb_begin = sp * chunk;
    int kb_end = min(total, kb_begin + chunk);
    int pidx = gx * 8 + (int)blockIdx.y;

    int h = blockIdx.y;
    int tid = threadIdx.x;
    int w = tid >> 5;
    int l = tid & 31;
    int lb = l & 15;

    int q_cc = tid & 7, q_row = tid >> 3;
    auto issueQ = [&]() {
        #pragma unroll
        for (int t = 0; t < 4; t++) {
            int row = q_row + t * 32;
            size_t so = (size_t)(qb * 128 + row) * 1024 + h * 64 + q_cc * 8;
            CP16(sbase + (uint32_t)(row * AST + q_cc * 16), QK + so);
        }
    };
    auto issueKV = [&](int kb) {
        uint32_t base = sbase + QSZ + (uint32_t)((kb & 1) * KVBUF);
        #pragma unroll
        for (int t = 0; t < 2; t++) {
            int row = q_row + t * 32;
            uint32_t doff = (uint32_t)(row * AST + q_cc * 16);
            size_t sk = (size_t)(kb * 64 + row) * 1024 + 512 + h * 64 + q_cc * 8;
            CP16(base + doff, QK + sk);
            size_t sv = (size_t)(h * 64 + row) * S_LEN + kb * 64 + q_cc * 8;
            CP16(base + KSZ + doff, Vt + sv);
        }
    };

    issueQ();
    issueKV(kb_begin); CP_COMMIT();

    float o[8][4];
    #pragma unroll
    for (int j = 0; j < 8; j++)
        #pragma unroll
        for (int k = 0; k < 4; k++) o[j][k] = 0.f;
    float m0 = -1e30f, m1 = -1e30f, l0 = 0.f, l1 = 0.f;

    uint32_t aq = sbase + (uint32_t)((16 * w + lb) * AST) + (uint32_t)(l >> 4) * 16;
    uint32_t kv_rel = (uint32_t)(((l >> 4) * 8 + (l & 7)) * AST) + (uint32_t)((l >> 3) & 1) * 16;

    int row0g = qb * 128 + 16 * w + (l >> 2);

    for (int kb = kb_begin; kb < kb_end; kb++) {
        if (kb + 1 < kb_end) { issueKV(kb + 1); CP_COMMIT(); CP_WAIT1(); }
        else CP_WAIT0();
        __syncthreads();

        uint32_t kvb = sbase + QSZ + (uint32_t)((kb & 1) * KVBUF);
        uint32_t bk = kvb + kv_rel;
        uint32_t bv = kvb + KSZ + kv_rel;

        // ---- S = Q K^T (fp16 single-pass) ----
        float s[8][4];
        #pragma unroll
        for (int j = 0; j < 8; j++)
            #pragma unroll
            for (int k = 0; k < 4; k++) s[j][k] = 0.f;
        #pragma unroll
        for (int ks = 0; ks < 4; ks++) {
            uint32_t ah[4];
            LDMATRIX_X4(ah[0], ah[1], ah[2], ah[3], aq + ks * 32);
            #pragma unroll
            for (int jp = 0; jp < 4; jp++) {
                uint32_t bh[2][2];
                uint32_t ba = bk + jp * 16 * AST + ks * 32;
                LDMATRIX_X4(bh[0][0], bh[0][1], bh[1][0], bh[1][1], ba);
                MMA_F16(s[2 * jp], ah, bh[0]);
                MMA_F16(s[2 * jp + 1], ah, bh[1]);
            }
        }

        // ---- scale + causal mask ----
        int cbase = kb * 64 + 2 * (l & 3);
        bool need_mask = (kb >= 2 * qb);
        #pragma unroll
        for (int j = 0; j < 8; j++) {
            #pragma unroll
            for (int k = 0; k < 4; k++) s[j][k] *= 0.125f;
            if (need_mask) {
                int c0 = cbase + 8 * j;
                if (c0 > row0g)     s[j][0] = -1e30f;
                if (c0 + 1 > row0g) s[j][1] = -1e30f;
                if (c0 > row0g + 8)     s[j][2] = -1e30f;
                if (c0 + 1 > row0g + 8) s[j][3] = -1e30f;
            }
        }

        // ---- online softmax ----
        float mn0 = m0, mn1 = m1;
        #pragma unroll
        for (int j = 0; j < 8; j++) {
            mn0 = fmaxf(mn0, fmaxf(s[j][0], s[j][1]));
            mn1 = fmaxf(mn1, fmaxf(s[j][2], s[j][3]));
        }
        mn0 = fmaxf(mn0, __shfl_xor_sync(0xffffffffu, mn0, 1));
        mn0 = fmaxf(mn0, __shfl_xor_sync(0xffffffffu, mn0, 2));
        mn1 = fmaxf(mn1, __shfl_xor_sync(0xffffffffu, mn1, 1));
        mn1 = fmaxf(mn1, __shfl_xor_sync(0xffffffffu, mn1, 2));
        float alpha0 = __expf(m0 - mn0);
        float alpha1 = __expf(m1 - mn1);
        m0 = mn0; m1 = mn1;
        float rs0 = 0.f, rs1 = 0.f;
        #pragma unroll
        for (int j = 0; j < 8; j++) {
            s[j][0] = __expf(s[j][0] - mn0);
            s[j][1] = __expf(s[j][1] - mn0);
            s[j][2] = __expf(s[j][2] - mn1);
            s[j][3] = __expf(s[j][3] - mn1);
            rs0 += s[j][0] + s[j][1];
            rs1 += s[j][2] + s[j][3];
        }
        l0 = l0 * alpha0 + rs0;
        l1 = l1 * alpha1 + rs1;
        #pragma unroll
        for (int j = 0; j < 8; j++) {
            o[j][0] *= alpha0; o[j][1] *= alpha0;
            o[j][2] *= alpha1; o[j][3] *= alpha1;
        }

        // ---- O += P @ V (fp16 single-pass) ----
        #pragma unroll
        for (int ks = 0; ks < 4; ks++) {
            uint32_t pa[4];
            pa[0] = pack_f16(s[2 * ks][0], s[2 * ks][1]);
            pa[1] = pack_f16(s[2 * ks][2], s[2 * ks][3]);
            pa[2] = pack_f16(s[2 * ks + 1][0], s[2 * ks + 1][1]);
            pa[3] = pack_f16(s[2 * ks + 1][2], s[2 * ks + 1][3]);
            #pragma unroll
            for (int jp = 0; jp < 4; jp++) {
                uint32_t vh[2][2];
                uint32_t va = bv + jp * 16 * AST + ks * 32;
                LDMATRIX_X4(vh[0][0], vh[0][1], vh[1][0], vh[1][1], va);
                MMA_F16(o[2 * jp], pa, vh[0]);
                MMA_F16(o[2 * jp + 1], pa, vh[1]);
            }
        }
        __syncthreads();
    }

    // ---- finalize ----
    l0 += __shfl_xor_sync(0xffffffffu, l0, 1);
    l0 += __shfl_xor_sync(0xffffffffu, l0, 2);
    l1 += __shfl_xor_sync(0xffffffffu, l1, 1);
    l1 += __shfl_xor_sync(0xffffffffu, l1, 2);

    if (nsp == 1) {
        float inv0 = 1.f / l0, inv1 = 1.f / l1;
        #pragma unroll
        for (int j = 0; j < 8; j++) {
            int col = h * 64 + 8 * j + 2 * (l & 3);
            *(uint32_t*)(AO + (size_t)row0g * D_DIM + col) = pack_f16(o[j][0] * inv0, o[j][1] * inv0);
            *(uint32_t*)(AO + (size_t)(row0g + 8) * D_DIM + col) = pack_f16(o[j][2] * inv1, o[j][3] * inv1);
        }
    } else {
        float* po = Po + (size_t)pidx * 8192;
        float* pml = Pml + (size_t)pidx * 256;
        int r0 = 16 * w + (l >> 2);
        #pragma unroll
        for (int j = 0; j < 8; j++) {
            int c = 8 * j + 2 * (l & 3);
            float2 v0; v0.x = o[j][0]; v0.y = o[j][1];
            float2 v1; v1.x = o[j][2]; v1.y = o[j][3];
            *(float2*)(po + r0 * 64 + c) = v0;
            *(float2*)(po + (r0 + 8) * 64 + c) = v1;
        }
        if ((l & 3) == 0) {
            pml[r0 * 2] = m0; pml[r0 * 2 + 1] = l0;
            pml[(r0 + 8) * 2] = m1; pml[(r0 + 8) * 2 + 1] = l1;
        }
    }
}

// ---------------- split-K combine (qb >= 4) ----------------
__global__ void attn_combine(const float* __restrict__ Po, const float* __restrict__ Pml,
                             f16* __restrict__ AO) {
    int qb = 4 + (int)blockIdx.x;
    int h = blockIdx.y;
    int nsp = nsp_of(qb);
    int base = 0;
    for (int i = 0; i < qb; i++) base += nsp_of(i);
    int tid = threadIdx.x;
    int row = tid >> 1;
    int c0 = (tid & 1) * 32;

    float mi[8], li[8], wgt[8];
    float mg = -1e30f;
    for (int i = 0; i < nsp; i++) {
        const float* pml = Pml + (size_t)((base + i) * 8 + h) * 256;
        mi[i] = pml[row * 2];
        li[i] = pml[row * 2 + 1];
        mg = fmaxf(mg, mi[i]);
    }
    float L = 0.f;
    for (int i = 0; i < nsp; i++) { wgt[i] = __expf(mi[i] - mg); L += li[i] * wgt[i]; }
    float invL = 1.f / L;

    size_t orow = (size_t)(qb * 128 + row) * D_DIM + h * 64;
    for (int c = c0; c < c0 + 32; c += 2) {
        float x = 0.f, y = 0.f;
        for (int i = 0; i < nsp; i++) {
            const float* p = Po + (size_t)((base + i) * 8 + h) * 8192 + row * 64 + c;
            x += p[0] * wgt[i];
            y += p[1] * wgt[i];
        }
        *(uint32_t*)(AO + orow + c) = pack_f16(x * invL, y * invL);
    }
}

// ---------------- launch ----------------
extern "C" void kernel_launch(void* const* d_in, const int* in_sizes, int n_in,
                              void* d_out, int out_size) {
    const float* x    = (const float*)d_in[0];
    const float* wqkv = (const float*)d_in[1];
    const float* bqkv = (const float*)d_in[2];
    const float* wout = (const float*)d_in[3];
    const float* bout = (const float*)d_in[4];
    const float* wff1 = (const float*)d_in[5];
    const float* bff1 = (const float*)d_in[6];
    const float* wff2 = (const float*)d_in[7];
    const float* bff2 = (const float*)d_in[8];
    const float* g1   = (const float*)d_in[9];
    const float* bt1  = (const float*)d_in[10];
    const float* g2   = (const float*)d_in[11];
    const float* bt2  = (const float*)d_in[12];
    float* out = (float*)d_out;

    f16 *hp, *wqT, *woT, *w1T, *w2T, *qk, *vt, *ao, *h2, *ff;
    float *x1, *po, *pml;
    cudaGetSymbolAddress((void**)&hp,  g_h);
    cudaGetSymbolAddress((void**)&wqT, g_wqkvT);
    cudaGetSymbolAddress((void**)&woT, g_woutT);
    cudaGetSymbolAddress((void**)&w1T, g_wff1T);
    cudaGetSymbolAddress((void**)&w2T, g_wff2T);
    cudaGetSymbolAddress((void**)&qk,  g_qk);
    cudaGetSymbolAddress((void**)&vt,  g_vt);
    cudaGetSymbolAddress((void**)&ao,  g_ao);
    cudaGetSymbolAddress((void**)&h2,  g_h2);
    cudaGetSymbolAddress((void**)&ff,  g_ff);
    cudaGetSymbolAddress((void**)&x1,  g_x1);
    cudaGetSymbolAddress((void**)&po,  g_po);
    cudaGetSymbolAddress((void**)&pml, g_pml);

    const int GS128 = 3 * (128 * 80 + 128 * 80);   // 61440
    const int GS64  = 3 * (128 * 80 + 64 * 80);    // 46080
    cudaFuncSetAttribute(gemm1<128, 512, 0>, cudaFuncAttributeMaxDynamicSharedMemorySize, GS128);
    cudaFuncSetAttribute(gemm1<128, 512, 1>, cudaFuncAttributeMaxDynamicSharedMemorySize, GS128);
    cudaFuncSetAttribute(gemm1<64, 512, 2>,  cudaFuncAttributeMaxDynamicSharedMemorySize, GS64);
    cudaFuncSetAttribute(gemm1<64, 1024, 2>, cudaFuncAttributeMaxDynamicSharedMemorySize, GS64);
    cudaFuncSetAttribute(attn_cp, cudaFuncAttributeMaxDynamicSharedMemorySize, ATT_SMEM);

    // 0) weight prep (fp16)
    wprep4<<<2048, 256>>>(wqkv, wqT, wout, woT, wff1, w1T, wff2, w2T);
    // 1) h = LN1(x) -> fp16
    ln_f16<<<S_LEN, 256>>>(x, g1, bt1, hp);
    // 2) qkv (fp16) -> qk + vt
    gemm1<128, 512, 0><<<dim3(12, 32), 256, GS128>>>(hp, wqT, bqkv, nullptr,
        nullptr, qk, vt, 1536);
    // 3) attention -> ao
    attn_cp<<<dim3(144, 8), 256, ATT_SMEM>>>(qk, vt, ao, po, pml);
    attn_combine<<<dim3(28, 8), 256>>>(po, pml, ao);
    // 4) x1 = x + ao @ w_out + b_out
    gemm1<64, 512, 2><<<dim3(8, 32), 256, GS64>>>(ao, woT, bout, x, x1,
        nullptr, nullptr, 512);
    // 5) h2 = LN2(x1) -> fp16
    ln_f16<<<S_LEN, 256>>>(x1, g2, bt2, h2);
    // 6) ff = gelu(h2 @ w_ff1 + b_ff1) -> fp16
    gemm1<128, 512, 1><<<dim3(8, 32), 256, GS128>>>(h2, w1T, bff1, nullptr,
        nullptr, ff, nullptr, 1024);
    // 7) out = x1 + ff @ w_ff2 + b_ff2
    gemm1<64, 1024, 2><<<dim3(8, 32), 256, GS64>>>(ff, w2T, bff2, x1, out,
        nullptr, nullptr, 512);
}